// round 15
// baseline (speedup 1.0000x reference)
#include <cuda_runtime.h>
#include <cuda_fp16.h>
#include <math.h>
#include <stdint.h>

#define BATCHN 32
#define LSEQ   196
#define DM     384
#define DI     768
#define DS     16
#define DTR    24
#define DBCN   56
#define DEPTH  12
#define MROWS  (BATCHN*LSEQ)   // 6272
#define MTILES 49

#if defined(__CUDA_ARCH__) && (defined(__CUDA_ARCH_FEAT_SM103_ALL) || defined(__CUDA_ARCH_SPECIFIC__))
#define HAS_TC 1
#else
#define HAS_TC 0
#endif

typedef __half f16;

// ---------------- scratch ----------------
__device__ __align__(256) float g_x  [MROWS*DM];
__device__ __align__(256) float g_xz [2*MROWS*2*DI];      // also reused as final-LN scratch
__device__ __align__(256) float g_dbc[2*MROWS*DBCN];
__device__ __align__(256) float g_dt [2*MROWS*DI];

__device__ __align__(256) f16 g_xn_h[MROWS*DM];
__device__ __align__(256) f16 g_im_h[MROWS*768];
__device__ __align__(256) f16 g_u_h [2*MROWS*DI],  g_u_l [2*MROWS*DI];
__device__ __align__(256) f16 g_y_h [MROWS*2*DI];
__device__ __align__(256) f16 g_dbch[2*MROWS*DBCN + 128], g_dbcl[2*MROWS*DBCN + 128];
__device__ __align__(256) f16 g_inw_h [DEPTH*2*2*DI*DM];
__device__ __align__(256) f16 g_outw_h[DEPTH*DM*2*DI];
__device__ __align__(256) f16 g_xpw_h [DEPTH*2*64*DI],   g_xpw_l [DEPTH*2*64*DI];
__device__ __align__(256) f16 g_dtw_h [DEPTH*2*DI*64],   g_dtw_l [DEPTH*2*DI*64]; // cols>=24 zero
__device__ __align__(256) f16 g_pw_h  [DM*768];

__device__ __forceinline__ void split2(float v, f16& h, f16& l) {
    h = __float2half_rn(v);
    l = __float2half_rn(v - __half2float(h));
}

#if HAS_TC
__device__ __forceinline__ uint32_t smem_u32(const void* p) {
    uint32_t a;
    asm("{ .reg .u64 t; cvta.to.shared.u64 t, %1; cvt.u32.u64 %0, t; }" : "=r"(a) : "l"(p));
    return a;
}
__device__ __forceinline__ uint32_t elect_one() {
    uint32_t p;
    asm volatile("{ .reg .pred p; elect.sync _|p, 0xFFFFFFFF; selp.b32 %0,1,0,p; }" : "=r"(p));
    return p;
}
#define SWZ(o) ((o) ^ (((o) >> 3) & 0x70))

static __device__ __forceinline__ uint64_t make_desc(uint32_t addr) {
    const uint64_t base =
        (uint64_t(2) << 61) | (uint64_t(1) << 46) | (uint64_t(64) << 32) | (uint64_t(1) << 16);
    return base | ((uint64_t)(addr >> 4) & 0x3FFF);
}

#define MBAR_INIT(a, c) \
    asm volatile("mbarrier.init.shared.b64 [%0], %1;" :: "r"(a), "r"(c) : "memory")
#define MBAR_INVAL(a) \
    asm volatile("mbarrier.inval.shared.b64 [%0];" :: "r"(a) : "memory")
#define MBAR_WAIT(a, ph) do {                                            \
    uint32_t _m = (a); uint32_t _p = (ph); uint32_t _d;                  \
    asm volatile("{ .reg .pred p; mbarrier.try_wait.parity.acquire.cta.shared::cta.b64 p,[%1],%2; selp.b32 %0,1,0,p; }" \
        : "=r"(_d) : "r"(_m), "r"(_p) : "memory");                       \
    if (!_d) {                                                           \
        asm volatile("{ .reg .pred P1; W%=: mbarrier.try_wait.parity.acquire.cta.shared::cta.b64 P1,[%0],%1,0x989680; @P1 bra.uni D%=; bra.uni W%=; D%=: }" \
            :: "r"(_m), "r"(_p) : "memory");                             \
    } } while (0)

#define CP_ASYNC16(dst, src) \
    asm volatile("cp.async.cg.shared.global [%0], [%1], 16;" :: "r"(dst), "l"(src) : "memory")
#define CP_COMMIT() asm volatile("cp.async.commit_group;" ::: "memory")
#define CP_WAIT1()  asm volatile("cp.async.wait_group 1;" ::: "memory")

__device__ __forceinline__ void tc_alloc(uint32_t smem_dst, uint32_t ncols) {
    asm volatile("tcgen05.alloc.cta_group::1.sync.aligned.shared::cta.b32 [%0], %1;"
                 :: "r"(smem_dst), "r"(ncols) : "memory");
}
__device__ __forceinline__ void tc_relinq() {
    asm volatile("tcgen05.relinquish_alloc_permit.cta_group::1.sync.aligned;");
}
__device__ __forceinline__ void tc_dealloc(uint32_t tmem, uint32_t ncols) {
    asm volatile("tcgen05.dealloc.cta_group::1.sync.aligned.b32 %0, %1;" :: "r"(tmem), "r"(ncols));
}
__device__ __forceinline__ void tc_commit(uint32_t mbar) {
    asm volatile("tcgen05.commit.cta_group::1.mbarrier::arrive::one.shared::cluster.b64 [%0];"
                 :: "r"(mbar) : "memory");
}
__device__ __forceinline__ void mma_f16(uint32_t d, uint64_t ad, uint64_t bd, uint32_t idesc, bool acc) {
    uint32_t en = acc ? 1u : 0u, z = 0u;
    asm volatile(
        "{ .reg .pred p; setp.ne.u32 p, %5, 0;"
        " tcgen05.mma.cta_group::1.kind::f16 [%0], %1, %2, %3, {%4,%4,%4,%4}, p; }"
        :: "r"(d), "l"(ad), "l"(bd), "r"(idesc), "r"(z), "r"(en) : "memory");
}
#define TC_LD_X32(r, a)                                                     \
    asm volatile("tcgen05.ld.sync.aligned.32x32b.x32.b32 "                  \
        "{%0,%1,%2,%3,%4,%5,%6,%7,%8,%9,%10,%11,%12,%13,%14,%15,"           \
        "%16,%17,%18,%19,%20,%21,%22,%23,%24,%25,%26,%27,%28,%29,%30,%31}, [%32];" \
        : "=r"((r)[0]),"=r"((r)[1]),"=r"((r)[2]),"=r"((r)[3]),"=r"((r)[4]),"=r"((r)[5]),"=r"((r)[6]),"=r"((r)[7]), \
          "=r"((r)[8]),"=r"((r)[9]),"=r"((r)[10]),"=r"((r)[11]),"=r"((r)[12]),"=r"((r)[13]),"=r"((r)[14]),"=r"((r)[15]), \
          "=r"((r)[16]),"=r"((r)[17]),"=r"((r)[18]),"=r"((r)[19]),"=r"((r)[20]),"=r"((r)[21]),"=r"((r)[22]),"=r"((r)[23]), \
          "=r"((r)[24]),"=r"((r)[25]),"=r"((r)[26]),"=r"((r)[27]),"=r"((r)[28]),"=r"((r)[29]),"=r"((r)[30]),"=r"((r)[31]) \
        : "r"(a))
#define TC_WAIT_LD() asm volatile("tcgen05.wait::ld.sync.aligned;" ::: "memory")
#define TC_FENCE_AFTER() asm volatile("tcgen05.fence::after_thread_sync;" ::: "memory")

// ---- packed f32x2 helpers (sm_103a) ----
__device__ __forceinline__ uint64_t pk2(float lo, float hi) {
    uint64_t r; asm("mov.b64 %0, {%1, %2};" : "=l"(r) : "f"(lo), "f"(hi)); return r;
}
__device__ __forceinline__ void upk2(uint64_t v, float& lo, float& hi) {
    asm("mov.b64 {%0, %1}, %2;" : "=f"(lo), "=f"(hi) : "l"(v));
}
__device__ __forceinline__ uint64_t mul2(uint64_t a, uint64_t b) {
    uint64_t r; asm("mul.rn.f32x2 %0, %1, %2;" : "=l"(r) : "l"(a), "l"(b)); return r;
}
__device__ __forceinline__ uint64_t fma2(uint64_t a, uint64_t b, uint64_t c) {
    uint64_t r; asm("fma.rn.f32x2 %0, %1, %2, %3;" : "=l"(r) : "l"(a), "l"(b), "l"(c)); return r;
}
#endif  // HAS_TC

__device__ __forceinline__ float softplusf(float v) {
    return (v > 0.f) ? v + log1pf(__expf(-v)) : log1pf(__expf(v));
}

// =====================================================================
// fp16 tcgen05 GEMM, 3-stage cp.async ring, 256 threads (R13-proven).
// EPI: 0 plain, 2 v+res, 3 v+bias+res[(m%L)*ldc+col]
// =====================================================================
template<int NT, int EPI, bool ASPLIT, bool BSPLIT, bool SPLITOUT>
__global__ void __launch_bounds__(256) mma_gemm(
    const f16* __restrict__ Ah, const f16* __restrict__ Al, int lda, long sA,
    const f16* __restrict__ Bh, const f16* __restrict__ Bl, int ldb, long sB,
    float* __restrict__ C, int ldc, long sC, int Ncols,
    int S,
    const float* __restrict__ bias, long sBias,
    const float* __restrict__ res,
    f16* __restrict__ Ch, f16* __restrict__ Cl)
{
    const int tid = threadIdx.x;
    const int m0 = blockIdx.y * 128, n0 = blockIdx.x * NT;
    Ah += (size_t)blockIdx.z * sA;
    if (ASPLIT) Al += (size_t)blockIdx.z * sA;
    Bh += (size_t)blockIdx.z * sB;
    if (BSPLIT) Bl += (size_t)blockIdx.z * sB;
    C  += (size_t)blockIdx.z * sC;
    if (bias) bias += (size_t)blockIdx.z * sBias;
    if (SPLITOUT) { Ch += (size_t)blockIdx.z * sC; Cl += (size_t)blockIdx.z * sC; }

#if HAS_TC
    extern __shared__ char smem[];
    const uint32_t sb = smem_u32(smem);
    const int wid = tid >> 5, lane = tid & 31;
    constexpr int ABYTES = 128 * 128;
    constexpr int BBYTES = NT * 128;
    constexpr int NA     = ASPLIT ? 2 : 1;
    constexpr int NB     = BSPLIT ? 2 : 1;
    constexpr int STAGE  = NA * ABYTES + NB * BBYTES;

    if (tid == 0) {
#pragma unroll
        for (int i = 0; i < 3; i++) MBAR_INIT(sb + 8 + i * 8, 1);
    }
    if (wid == 0) { tc_alloc(sb, NT); tc_relinq(); }
    __syncthreads();
    uint32_t tmem;
    asm volatile("ld.shared.b32 %0, [%1];" : "=r"(tmem) : "r"(sb));

    const uint32_t idesc = 0x10u | ((uint32_t)(NT / 8) << 17) | (8u << 24);

    auto stage_load = [&](int r, int step) {
        const int k0 = step << 6;
        const uint32_t ah = sb + 1024 + r * STAGE;
        const uint32_t al = ah + ABYTES;
        const uint32_t bh = ah + NA * ABYTES;
        const uint32_t bl = bh + BBYTES;
#pragma unroll
        for (int i = 0; i < 4; i++) {
            int c = i * 256 + tid; int row = c >> 3, q = c & 7;
            uint32_t so = SWZ(row * 128 + q * 16);
            size_t go = (size_t)(m0 + row) * lda + k0 + q * 8;
            CP_ASYNC16(ah + so, Ah + go);
            if (ASPLIT) CP_ASYNC16(al + so, Al + go);
        }
#pragma unroll
        for (int i = 0; i < NT / 32; i++) {
            int c = i * 256 + tid; int row = c >> 3, q = c & 7;
            uint32_t so = SWZ(row * 128 + q * 16);
            size_t go = (size_t)(n0 + row) * ldb + k0 + q * 8;
            CP_ASYNC16(bh + so, Bh + go);
            if (BSPLIT) CP_ASYNC16(bl + so, Bl + go);
        }
    };

#pragma unroll
    for (int p = 0; p < 3; p++) { if (p < S) stage_load(p, p); CP_COMMIT(); }

    int ph[3] = {0, 0, 0};
    for (int s = 0; s < S; s++) {
        CP_WAIT1();
        asm volatile("fence.proxy.async.shared::cta;" ::: "memory");
        __syncthreads();
        const int st = s % 3;
        if (wid == 0 && elect_one()) {
            const uint32_t ah = sb + 1024 + st * STAGE;
            uint64_t adh = make_desc(ah);
            uint64_t bdh = make_desc(ah + NA * ABYTES);
#pragma unroll
            for (int sl = 0; sl < 4; sl++)
                mma_f16(tmem, adh + sl * 2, bdh + sl * 2, idesc, (s > 0) || (sl > 0));
            if (ASPLIT) {
                uint64_t adl = make_desc(ah + ABYTES);
#pragma unroll
                for (int sl = 0; sl < 4; sl++)
                    mma_f16(tmem, adl + sl * 2, bdh + sl * 2, idesc, true);
            }
            if (BSPLIT) {
                uint64_t bdl = make_desc(ah + NA * ABYTES + BBYTES);
#pragma unroll
                for (int sl = 0; sl < 4; sl++)
                    mma_f16(tmem, adh + sl * 2, bdl + sl * 2, idesc, true);
            }
            tc_commit(sb + 8 + st * 8);
        }
        if (s >= 1 && s + 2 < S) {
            const int r = (s + 2) % 3;
            MBAR_WAIT(sb + 8 + r * 8, ph[r]); ph[r] ^= 1;
            stage_load(r, s + 2);
        }
        CP_COMMIT();
    }
    MBAR_WAIT(sb + 8 + ((S - 1) % 3) * 8, ph[(S - 1) % 3]);
    TC_FENCE_AFTER();

    const int subp = wid & 3, half = wid >> 2;
#pragma unroll
    for (int ch = 0; ch < NT / 64; ch++) {
        const int chunk = half * (NT / 64) + ch;
        uint32_t r[32];
        TC_LD_X32(r, tmem + chunk * 32);
        TC_WAIT_LD();
        const int row = m0 + subp * 32 + lane;
        const int col0 = n0 + chunk * 32;
        float* cp = C + (size_t)row * ldc + col0;
        float vals[32];
#pragma unroll
        for (int j = 0; j < 32; j++) {
            float v = __uint_as_float(r[j]);
            const int col = col0 + j;
            if (EPI == 2) v += res[(size_t)row * ldc + col];
            if (EPI == 3) v += bias[col] + res[(size_t)(row % LSEQ) * ldc + col];
            vals[j] = v;
        }
        if (col0 + 31 < Ncols) {
#pragma unroll
            for (int g = 0; g < 8; g++)
                *(float4*)(cp + g * 4) =
                    make_float4(vals[4*g], vals[4*g+1], vals[4*g+2], vals[4*g+3]);
            if (SPLITOUT) {
#pragma unroll
                for (int j = 0; j < 32; j++) {
                    f16 hh, ll; split2(vals[j], hh, ll);
                    Ch[(size_t)row * ldc + col0 + j] = hh;
                    Cl[(size_t)row * ldc + col0 + j] = ll;
                }
            }
        } else {
#pragma unroll
            for (int j = 0; j < 32; j++)
                if (col0 + j < Ncols) {
                    cp[j] = vals[j];
                    if (SPLITOUT) {
                        f16 hh, ll; split2(vals[j], hh, ll);
                        Ch[(size_t)row * ldc + col0 + j] = hh;
                        Cl[(size_t)row * ldc + col0 + j] = ll;
                    }
                }
        }
    }
    __syncthreads();
    if (tid == 0) {
#pragma unroll
        for (int i = 0; i < 3; i++) MBAR_INVAL(sb + 8 + i * 8);
    }
    if (wid == 0) tc_dealloc(tmem, NT);
#else
    if (tid >= 128) return;
    const int row = m0 + tid;
    const int K = S * 64;
    for (int n = 0; n < NT; n++) {
        const int col = n0 + n;
        if (col >= Ncols) break;
        float acc = 0.f;
        for (int k = 0; k < K; k++) {
            float a = __half2float(Ah[(size_t)row * lda + k]);
            if (ASPLIT) a += __half2float(Al[(size_t)row * lda + k]);
            float b = __half2float(Bh[(size_t)col * ldb + k]);
            if (BSPLIT) b += __half2float(Bl[(size_t)col * ldb + k]);
            acc = fmaf(a, b, acc);
        }
        float v = acc;
        if (EPI == 2) v += res[(size_t)row * ldc + col];
        if (EPI == 3) v += bias[col] + res[(size_t)(row % LSEQ) * ldc + col];
        C[(size_t)row * ldc + col] = v;
        if (SPLITOUT) {
            f16 hh, ll; split2(v, hh, ll);
            Ch[(size_t)row * ldc + col] = hh;
            Cl[(size_t)row * ldc + col] = ll;
        }
    }
#endif
}

// =====================================================================
// dt GEMM: dt = softplus(dbc[:, :24] @ dt_w + dt_b)
// K=64 (zero-padded), M-looped: each CTA does several M-tiles, B loaded
// once, TMEM allocated once, A double-buffered (prefetch overlaps MMA).
// grid (DI/128, NBY, 2), 256 threads.
// =====================================================================
__global__ void __launch_bounds__(256) dt_gemm(
    const f16* __restrict__ Ah, const f16* __restrict__ Al,   // dbch/dbcl, lda=DBCN
    const f16* __restrict__ Bh, const f16* __restrict__ Bl,   // dtw planes, ldb=64
    float* __restrict__ C,                                    // dtv, ldc=DI
    const float* __restrict__ bias)                           // dt_b
{
    const int tid = threadIdx.x;
    const int n0  = blockIdx.x * 128;
    const int dir = blockIdx.z;
    Ah += (size_t)dir * MROWS * DBCN;
    Al += (size_t)dir * MROWS * DBCN;
    Bh += (size_t)dir * DI * 64;
    Bl += (size_t)dir * DI * 64;
    C  += (size_t)dir * MROWS * DI;
    bias += (size_t)dir * DI;

#if HAS_TC
    extern __shared__ char smem[];
    const uint32_t sb = smem_u32(smem);
    const int wid = tid >> 5, lane = tid & 31;
    // layout: [0:4) tmem ptr, [8:16) mbar, B @1024 (2x16KB), A slots @33792 (2 slots x 2x16KB)
    const uint32_t BOFF = sb + 1024;
    const uint32_t AOFF = sb + 1024 + 32768;

    if (tid == 0) MBAR_INIT(sb + 8, 1);
    if (wid == 0) { tc_alloc(sb, 128); tc_relinq(); }
    __syncthreads();
    uint32_t tmem;
    asm volatile("ld.shared.b32 %0, [%1];" : "=r"(tmem) : "r"(sb));

    const uint32_t idesc = 0x10u | (16u << 17) | (8u << 24);   // N=128, M=128

    // load B (both planes) once: 128 rows x 64 f16 per plane
    {
#pragma unroll
        for (int i = 0; i < 4; i++) {
            int c = i * 256 + tid; int row = c >> 3, q = c & 7;
            uint32_t so = SWZ(row * 128 + q * 16);
            size_t go = (size_t)(n0 + row) * 64 + q * 8;
            CP_ASYNC16(BOFF + so, Bh + go);
            CP_ASYNC16(BOFF + 16384 + so, Bl + go);
        }
        CP_COMMIT();
    }

    auto load_A = [&](int slot, int mt) {
        const int m0 = mt * 128;
        const uint32_t a = AOFF + slot * 32768;
#pragma unroll
        for (int i = 0; i < 4; i++) {
            int c = i * 256 + tid; int row = c >> 3, q = c & 7;
            uint32_t so = SWZ(row * 128 + q * 16);
            size_t go = (size_t)(m0 + row) * DBCN + q * 8;   // overreads cols 56..63; B zero there
            CP_ASYNC16(a + so, Ah + go);
            CP_ASYNC16(a + 16384 + so, Al + go);
        }
    };

    // prefetch first A into slot 0
    int mt0 = blockIdx.y;
    load_A(0, mt0);
    CP_COMMIT();

    int ph = 0;
    int it = 0;
    for (int mt = mt0; mt < MTILES; mt += gridDim.y, it++) {
        const int cs = it & 1;
        // prefetch next tile into other slot
        const int nmt = mt + gridDim.y;
        if (nmt < MTILES) load_A(cs ^ 1, nmt);
        CP_COMMIT();
        CP_WAIT1();   // everything except the just-committed prefetch
        asm volatile("fence.proxy.async.shared::cta;" ::: "memory");
        __syncthreads();

        if (wid == 0 && elect_one()) {
            const uint32_t a = AOFF + cs * 32768;
            uint64_t adh = make_desc(a);
            uint64_t adl = make_desc(a + 16384);
            uint64_t bdh = make_desc(BOFF);
            uint64_t bdl = make_desc(BOFF + 16384);
#pragma unroll
            for (int sl = 0; sl < 4; sl++)
                mma_f16(tmem, adh + sl * 2, bdh + sl * 2, idesc, sl > 0);
#pragma unroll
            for (int sl = 0; sl < 4; sl++)
                mma_f16(tmem, adl + sl * 2, bdh + sl * 2, idesc, true);
#pragma unroll
            for (int sl = 0; sl < 4; sl++)
                mma_f16(tmem, adh + sl * 2, bdl + sl * 2, idesc, true);
            tc_commit(sb + 8);
        }
        MBAR_WAIT(sb + 8, ph); ph ^= 1;
        TC_FENCE_AFTER();

        const int subp = wid & 3, half = wid >> 2;
        const int m0 = mt * 128;
#pragma unroll
        for (int ch = 0; ch < 2; ch++) {
            const int chunk = half * 2 + ch;
            uint32_t r[32];
            TC_LD_X32(r, tmem + chunk * 32);
            TC_WAIT_LD();
            const int row = m0 + subp * 32 + lane;
            const int col0 = n0 + chunk * 32;
            float* cp = C + (size_t)row * DI + col0;
            float vals[32];
#pragma unroll
            for (int j = 0; j < 32; j++)
                vals[j] = softplusf(__uint_as_float(r[j]) + bias[col0 + j]);
#pragma unroll
            for (int g = 0; g < 8; g++)
                *(float4*)(cp + g * 4) =
                    make_float4(vals[4*g], vals[4*g+1], vals[4*g+2], vals[4*g+3]);
        }
        __syncthreads();   // all warps done reading TMEM before next MMA resets it
    }
    if (tid == 0) MBAR_INVAL(sb + 8);
    if (wid == 0) tc_dealloc(tmem, 128);
#else
    // SIMT fallback
    if (tid >= 128) return;
    for (int mt = blockIdx.y; mt < MTILES; mt += gridDim.y) {
        const int row = mt * 128 + tid;
        for (int n = 0; n < 128; n++) {
            const int col = n0 + n;
            float acc = 0.f;
            for (int k = 0; k < DTR; k++) {
                float a = __half2float(Ah[(size_t)row * DBCN + k]) +
                          __half2float(Al[(size_t)row * DBCN + k]);
                float b = __half2float(Bh[(size_t)col * 64 + k]) +
                          __half2float(Bl[(size_t)col * 64 + k]);
                acc = fmaf(a, b, acc);
            }
            C[(size_t)row * DI + col] = softplusf(acc + bias[col]);
        }
    }
#endif
}

// ---- transpose + zero-pad + fp16-split (two planes) ----
__global__ void __launch_bounds__(256) transpose_split(
    const float* __restrict__ in, f16* __restrict__ oh, f16* __restrict__ ol,
    int R, int C, int OR_, int OC)
{
    __shared__ float t[32][33];
    const int z = blockIdx.z;
    in += (size_t)z * R * C;
    oh += (size_t)z * OR_ * OC;
    ol += (size_t)z * OR_ * OC;
    const int j0 = blockIdx.x * 32;
    const int i0 = blockIdx.y * 32;
    const int tx = threadIdx.x & 31, ty = threadIdx.x >> 5;
#pragma unroll
    for (int k = 0; k < 4; k++) {
        int rin = j0 + ty + k * 8, cin = i0 + tx;
        t[ty + k * 8][tx] = (rin < R && cin < C) ? in[(size_t)rin * C + cin] : 0.f;
    }
    __syncthreads();
#pragma unroll
    for (int k = 0; k < 4; k++) {
        int orow = i0 + ty + k * 8, ocol = j0 + tx;
        if (orow < OR_ && ocol < OC) {
            f16 h, l; split2(t[tx][ty + k * 8], h, l);
            oh[(size_t)orow * OC + ocol] = h;
            ol[(size_t)orow * OC + ocol] = l;
        }
    }
}

// ---- transpose + fp16 single plane ----
__global__ void __launch_bounds__(256) transpose_h(
    const float* __restrict__ in, f16* __restrict__ oh, int R, int C)
{
    __shared__ float t[32][33];
    const int z = blockIdx.z;
    in += (size_t)z * R * C;
    oh += (size_t)z * R * C;
    const int j0 = blockIdx.x * 32;
    const int i0 = blockIdx.y * 32;
    const int tx = threadIdx.x & 31, ty = threadIdx.x >> 5;
#pragma unroll
    for (int k = 0; k < 4; k++)
        t[ty + k * 8][tx] = in[(size_t)(j0 + ty + k * 8) * C + i0 + tx];
    __syncthreads();
#pragma unroll
    for (int k = 0; k < 4; k++)
        oh[(size_t)(i0 + ty + k * 8) * R + j0 + tx] = __float2half_rn(t[tx][ty + k * 8]);
}

__global__ void half_copy(const float* __restrict__ in, f16* __restrict__ oh, int n)
{
    int i = blockIdx.x * blockDim.x + threadIdx.x;
    if (i < n) oh[i] = __float2half_rn(in[i]);
}

// ---------------- LayerNorm -> fp16 single ----------------
__global__ void __launch_bounds__(128) ln_kernel(
    const float* __restrict__ x, f16* __restrict__ yh,
    const float* __restrict__ g, const float* __restrict__ b)
{
    const int row = blockIdx.x;
    const int tid = threadIdx.x;
    const float* xr = x + (size_t)row * DM;
    float v0 = xr[tid], v1 = xr[tid + 128], v2 = xr[tid + 256];
    __shared__ float sh[4];
    float s = v0 + v1 + v2;
#pragma unroll
    for (int o = 16; o > 0; o >>= 1) s += __shfl_xor_sync(0xffffffffu, s, o);
    if ((tid & 31) == 0) sh[tid >> 5] = s;
    __syncthreads();
    float mu = (sh[0] + sh[1] + sh[2] + sh[3]) * (1.f / DM);
    float d0 = v0 - mu, d1 = v1 - mu, d2 = v2 - mu;
    float q = d0*d0 + d1*d1 + d2*d2;
    __syncthreads();
#pragma unroll
    for (int o = 16; o > 0; o >>= 1) q += __shfl_xor_sync(0xffffffffu, q, o);
    if ((tid & 31) == 0) sh[tid >> 5] = q;
    __syncthreads();
    float var = (sh[0] + sh[1] + sh[2] + sh[3]) * (1.f / DM);
    float rs = rsqrtf(var + 1e-5f);
    size_t base = (size_t)row * DM;
    yh[base + tid]       = __float2half_rn(d0 * rs * g[tid]       + b[tid]);
    yh[base + tid + 128] = __float2half_rn(d1 * rs * g[tid + 128] + b[tid + 128]);
    yh[base + tid + 256] = __float2half_rn(d2 * rs * g[tid + 256] + b[tid + 256]);
}

// ---------------- final LayerNorm -> fp32 ----------------
__global__ void __launch_bounds__(128) ln_f32(
    const float* __restrict__ x, float* __restrict__ y,
    const float* __restrict__ g, const float* __restrict__ b)
{
    const int row = blockIdx.x;
    const int tid = threadIdx.x;
    const float* xr = x + (size_t)row * DM;
    float v0 = xr[tid], v1 = xr[tid + 128], v2 = xr[tid + 256];
    __shared__ float sh[4];
    float s = v0 + v1 + v2;
#pragma unroll
    for (int o = 16; o > 0; o >>= 1) s += __shfl_xor_sync(0xffffffffu, s, o);
    if ((tid & 31) == 0) sh[tid >> 5] = s;
    __syncthreads();
    float mu = (sh[0] + sh[1] + sh[2] + sh[3]) * (1.f / DM);
    float d0 = v0 - mu, d1 = v1 - mu, d2 = v2 - mu;
    float q = d0*d0 + d1*d1 + d2*d2;
    __syncthreads();
#pragma unroll
    for (int o = 16; o > 0; o >>= 1) q += __shfl_xor_sync(0xffffffffu, q, o);
    if ((tid & 31) == 0) sh[tid >> 5] = q;
    __syncthreads();
    float var = (sh[0] + sh[1] + sh[2] + sh[3]) * (1.f / DM);
    float rs = rsqrtf(var + 1e-5f);
    float* yr = y + (size_t)row * DM;
    yr[tid]       = d0 * rs * g[tid]       + b[tid];
    yr[tid + 128] = d1 * rs * g[tid + 128] + b[tid + 128];
    yr[tid + 256] = d2 * rs * g[tid + 256] + b[tid + 256];
}

// ---------------- conv1d + SiLU, 4 channels/thread (R11-proven) ----------------
__global__ void conv_silu(const float* __restrict__ xz, const float* __restrict__ w,
                          const float* __restrict__ bias,
                          f16* __restrict__ uh, f16* __restrict__ ul)
{
    const int CQ = DI / 4;
    int idx = blockIdx.x * blockDim.x + threadIdx.x;
    if (idx >= 2 * MROWS * CQ) return;
    int q   = idx % CQ;  int c4 = q * 4;
    int m   = (idx / CQ) % MROWS;
    int dir = idx / (CQ * MROWS);
    int l = m % LSEQ, mbase = m - l;
    const float* xzd = xz + (size_t)dir * MROWS * 2 * DI;
    const float* wp = w + (size_t)dir * DI * 4 + c4 * 4;
    float4 w0 = *(const float4*)(wp);
    float4 w1 = *(const float4*)(wp + 4);
    float4 w2 = *(const float4*)(wp + 8);
    float4 w3 = *(const float4*)(wp + 12);
    float4 bv = *(const float4*)(bias + dir * DI + c4);
    float a0 = bv.x, a1 = bv.y, a2 = bv.z, a3 = bv.w;
    const float wk0[4] = {w0.x, w0.y, w0.z, w0.w};
    const float wk1[4] = {w1.x, w1.y, w1.z, w1.w};
    const float wk2[4] = {w2.x, w2.y, w2.z, w2.w};
    const float wk3[4] = {w3.x, w3.y, w3.z, w3.w};
#pragma unroll
    for (int k = 0; k < 4; k++) {
        int ls = dir ? (l + 3 - k) : (l - 3 + k);
        if (ls >= 0 && ls < LSEQ) {
            float4 xv = *(const float4*)(xzd + (size_t)(mbase + ls) * 2 * DI + c4);
            a0 = fmaf(wk0[k], xv.x, a0);
            a1 = fmaf(wk1[k], xv.y, a1);
            a2 = fmaf(wk2[k], xv.z, a2);
            a3 = fmaf(wk3[k], xv.w, a3);
        }
    }
    float u0 = a0 / (1.f + __expf(-a0));
    float u1 = a1 / (1.f + __expf(-a1));
    float u2 = a2 / (1.f + __expf(-a2));
    float u3 = a3 / (1.f + __expf(-a3));
    size_t o = (size_t)dir * MROWS * DI + (size_t)m * DI + c4;
    f16 h0,l0,h1,l1,h2,l2,h3,l3;
    split2(u0,h0,l0); split2(u1,h1,l1); split2(u2,h2,l2); split2(u3,h3,l3);
    __half2* uhp = (__half2*)(uh + o);
    __half2* ulp = (__half2*)(ul + o);
    uhp[0] = __halves2half2(h0, h1);
    uhp[1] = __halves2half2(h2, h3);
    ulp[0] = __halves2half2(l0, l1);
    ulp[1] = __halves2half2(l2, l3);
}

// ---------------- selective scan (packed f32x2 fast path) -> y fp16 ----------------
__global__ void __launch_bounds__(128) scan_kernel(
    const float* __restrict__ dt,
    const f16* __restrict__ uh, const f16* __restrict__ ul,
    const float* __restrict__ dbc, const float* __restrict__ xz,
    const float* __restrict__ A_log, const float* __restrict__ Dp,
    f16* __restrict__ yh)
{
    const int c   = blockIdx.x * 128 + threadIdx.x;
    const int b   = blockIdx.y;
    const int dir = blockIdx.z;

    __shared__ __align__(16) float Bsh[LSEQ][DS];
    __shared__ __align__(16) float Csh[LSEQ][DS];
    const float* dbcb = dbc + ((size_t)dir * MROWS + (size_t)b * LSEQ) * DBCN;
    for (int i = threadIdx.x; i < LSEQ * 2 * DS; i += 128) {
        int l = i >> 5, j = i & 31;
        float v = dbcb[(size_t)l * DBCN + DTR + j];
        if (j < DS) Bsh[l][j] = v; else Csh[l][j - DS] = v;
    }
    __syncthreads();

    float a[DS];
    const float* ap = A_log + ((size_t)dir * DI + c) * DS;
#pragma unroll
    for (int n = 0; n < DS; n++) a[n] = -__expf(ap[n]);
    const float a0 = a[0];
    bool fast = true;
#pragma unroll
    for (int n = 1; n < DS; n++)
        fast = fast && (fabsf(a[n] - a0 * (float)(n + 1)) <= 1e-4f * fabsf(a[n]));
    const float dp = Dp[dir * DI + c];

    const size_t ubase = ((size_t)dir * MROWS + (size_t)b * LSEQ) * DI + c;
    const float* dtb = dt + ubase;
    const float* zb  = xz + ((size_t)dir * MROWS + (size_t)b * LSEQ) * 2 * DI + DI + c;
    const size_t ybase = ((size_t)b * LSEQ) * 2 * DI + (size_t)dir * DI + c;

    int l = dir ? (LSEQ - 1) : 0;
    float dt_n = dtb[(size_t)l * DI];
    float uh_n = __half2float(uh[ubase + (size_t)l * DI]);
    float ul_n = __half2float(ul[ubase + (size_t)l * DI]);
    float z_n  = zb[(size_t)l * 2 * DI];

#if HAS_TC
    if (fast) {
        uint64_t h2[8];
#pragma unroll
        for (int k = 0; k < 8; k++) h2[k] = 0ull;
        for (int t = 0; t < LSEQ; t++) {
            const int lc = l;
            const float dtv = dt_n;
            const float uv  = uh_n + ul_n;
            const float zv  = z_n;
            if (t + 1 < LSEQ) {
                l = dir ? (LSEQ - 2 - t) : (t + 1);
                dt_n = dtb[(size_t)l * DI];
                uh_n = __half2float(uh[ubase + (size_t)l * DI]);
                ul_n = __half2float(ul[ubase + (size_t)l * DI]);
                z_n  = zb[(size_t)l * 2 * DI];
            }
            const float du = dtv * uv;
            const float e1 = __expf(dtv * a0);
            const float e2 = e1 * e1;
            const uint64_t E2  = pk2(e2, e2);
            const uint64_t du2 = pk2(du, du);
            uint64_t p = pk2(e1, e2);
            uint64_t acc2 = pk2(0.f, 0.f);
            const uint64_t* B2 = (const uint64_t*)&Bsh[lc][0];
            const uint64_t* C2 = (const uint64_t*)&Csh[lc][0];
#pragma unroll
            for (int k = 0; k < 8; k++) {
                if (k > 0) p = mul2(p, E2);
                uint64_t tmp = mul2(du2, B2[k]);
                h2[k] = fma2(p, h2[k], tmp);
                acc2 = fma2(h2[k], C2[k], acc2);
            }
            float alo, ahi; upk2(acc2, alo, ahi);
            const float yv = alo + ahi + dp * uv;
            const float og = yv * (zv / (1.f + __expf(-zv)));
            yh[ybase + (size_t)lc * 2 * DI] = __float2half_rn(og);
        }
        return;
    }
#endif
    float h[DS];
#pragma unroll
    for (int n = 0; n < DS; n++) h[n] = 0.f;
    for (int t = 0; t < LSEQ; t++) {
        const int lc = l;
        const float dtv = dt_n;
        const float uv  = uh_n + ul_n;
        const float zv  = z_n;
        if (t + 1 < LSEQ) {
            l = dir ? (LSEQ - 2 - t) : (t + 1);
            dt_n = dtb[(size_t)l * DI];
            uh_n = __half2float(uh[ubase + (size_t)l * DI]);
            ul_n = __half2float(ul[ubase + (size_t)l * DI]);
            z_n  = zb[(size_t)l * 2 * DI];
        }
        const float du = dtv * uv;
        float acc = 0.f;
        if (fast) {
            const float e1 = __expf(dtv * a0);
            float p = 1.f;
#pragma unroll
            for (int n = 0; n < DS; n++) {
                p *= e1;
                h[n] = p * h[n] + du * Bsh[lc][n];
                acc = fmaf(h[n], Csh[lc][n], acc);
            }
        } else {
#pragma unroll
            for (int n = 0; n < DS; n++) {
                h[n] = __expf(dtv * a[n]) * h[n] + du * Bsh[lc][n];
                acc = fmaf(h[n], Csh[lc][n], acc);
            }
        }
        const float yv = acc + dp * uv;
        const float og = yv * (zv / (1.f + __expf(-zv)));
        yh[ybase + (size_t)lc * 2 * DI] = __float2half_rn(og);
    }
}

// ---------------- pool + heads (after ln_f32) ----------------
__global__ void __launch_bounds__(384) pool_head(
    const float* __restrict__ fln,
    const float* __restrict__ wdev, const float* __restrict__ bdev,
    const float* __restrict__ wdist, const float* __restrict__ bdist,
    float* __restrict__ out)
{
    const int b = blockIdx.x;
    const int tid = threadIdx.x;
    __shared__ float pooled_s[DM];
    float s = 0.f;
    for (int l = 0; l < LSEQ; l++)
        s += fln[((size_t)b * LSEQ + l) * DM + tid];
    pooled_s[tid] = s * (1.f / LSEQ);
    __syncthreads();
    if (tid < 7) {
        float acc = bdev[tid];
        for (int d = 0; d < DM; d++) acc += pooled_s[d] * wdev[d * 7 + tid];
        out[b * 7 + tid] = acc;
    } else if (tid < 11) {
        int j = tid - 7;
        float acc = bdist[j];
        for (int d = 0; d < DM; d++) acc += pooled_s[d] * wdist[d * 4 + j];
        out[BATCHN * 7 + b * 4 + j] = acc;
    }
}

// ---------------- im2col -> fp16 single ----------------
__global__ void im2col_kernel(const float* __restrict__ img)
{
    int idx = blockIdx.x * blockDim.x + threadIdx.x;
    if (idx >= MROWS * 768) return;
    int k = idx % 768;
    int m = idx / 768;
    int b = m / LSEQ, l = m % LSEQ;
    int ph = l / 14, pw = l % 14;
    int ch  = k >> 8;
    int r   = (k >> 4) & 15;
    int col = k & 15;
    float v = img[(((size_t)b * 3 + ch) * 224 + ph * 16 + r) * 224 + pw * 16 + col];
    g_im_h[idx] = __float2half_rn(v);
}

// ---------------- launcher ----------------
extern "C" void kernel_launch(void* const* d_in, const int* in_sizes, int n_in,
                              void* d_out, int out_size)
{
    const float* images  = (const float*)d_in[0];
    const float* patch_w = (const float*)d_in[1];
    const float* patch_b = (const float*)d_in[2];
    const float* pos_emb = (const float*)d_in[3];
    const float* ln_g    = (const float*)d_in[4];
    const float* ln_b    = (const float*)d_in[5];
    const float* in_w    = (const float*)d_in[6];
    const float* conv_w  = (const float*)d_in[7];
    const float* conv_b  = (const float*)d_in[8];
    const float* xproj_w = (const float*)d_in[9];
    const float* dt_w    = (const float*)d_in[10];
    const float* dt_b    = (const float*)d_in[11];
    const float* A_log   = (const float*)d_in[12];
    const float* Dp      = (const float*)d_in[13];
    const float* out_w   = (const float*)d_in[14];
    const float* fln_g   = (const float*)d_in[15];
    const float* fln_b   = (const float*)d_in[16];
    const float* hdev_w  = (const float*)d_in[17];
    const float* hdev_b  = (const float*)d_in[18];
    const float* hdist_w = (const float*)d_in[19];
    const float* hdist_b = (const float*)d_in[20];
    float* out = (float*)d_out;

    float *x, *xz, *dbcv, *dtv;
    f16 *xn_h, *im_h, *u_h, *u_l, *y_h, *dbch, *dbcl;
    f16 *inw_h, *outw_h, *xpw_h, *xpw_l, *dtw_h, *dtw_l, *pw_h;
    cudaGetSymbolAddress((void**)&x,     g_x);
    cudaGetSymbolAddress((void**)&xz,    g_xz);
    cudaGetSymbolAddress((void**)&dbcv,  g_dbc);
    cudaGetSymbolAddress((void**)&dtv,   g_dt);
    cudaGetSymbolAddress((void**)&xn_h,  g_xn_h);
    cudaGetSymbolAddress((void**)&im_h,  g_im_h);
    cudaGetSymbolAddress((void**)&u_h,   g_u_h);   cudaGetSymbolAddress((void**)&u_l,   g_u_l);
    cudaGetSymbolAddress((void**)&y_h,   g_y_h);
    cudaGetSymbolAddress((void**)&dbch,  g_dbch);  cudaGetSymbolAddress((void**)&dbcl,  g_dbcl);
    cudaGetSymbolAddress((void**)&inw_h, g_inw_h);
    cudaGetSymbolAddress((void**)&outw_h,g_outw_h);
    cudaGetSymbolAddress((void**)&xpw_h, g_xpw_h); cudaGetSymbolAddress((void**)&xpw_l, g_xpw_l);
    cudaGetSymbolAddress((void**)&dtw_h, g_dtw_h); cudaGetSymbolAddress((void**)&dtw_l, g_dtw_l);
    cudaGetSymbolAddress((void**)&pw_h,  g_pw_h);

    const int SM_A1B1_128 = 1024 + 3 * (16384 + 16384);             // 99328  (2 CTAs/SM)
    const int SM_A2B2_64  = 1024 + 3 * (2 * 16384 + 2 * 64 * 128);  // 148480
    const int SM_DT       = 1024 + 32768 + 65536;                   // 99328  (2 CTAs/SM)
    cudaFuncSetAttribute(mma_gemm<128,0,false,false,false>, cudaFuncAttributeMaxDynamicSharedMemorySize, SM_A1B1_128);
    cudaFuncSetAttribute(mma_gemm<128,2,false,false,false>, cudaFuncAttributeMaxDynamicSharedMemorySize, SM_A1B1_128);
    cudaFuncSetAttribute(mma_gemm<128,3,false,false,false>, cudaFuncAttributeMaxDynamicSharedMemorySize, SM_A1B1_128);
    cudaFuncSetAttribute(mma_gemm<64,0,true,true,true>,     cudaFuncAttributeMaxDynamicSharedMemorySize, SM_A2B2_64);
    cudaFuncSetAttribute(dt_gemm,                            cudaFuncAttributeMaxDynamicSharedMemorySize, SM_DT);

    const int MT = MROWS / 128;  // 49

    // ---- weight packing ----
    transpose_h<<<dim3(12, 48, 24), 256>>>(in_w, inw_h, 384, 1536);
    transpose_h<<<dim3(48, 12, 12), 256>>>(out_w, outw_h, 1536, 384);
    half_copy<<<(DM*768 + 255)/256, 256>>>(patch_w, pw_h, DM*768);
    transpose_split<<<dim3(24, 2, 24), 256>>>(xproj_w, xpw_h, xpw_l, 768, 56, 64, 768);
    transpose_split<<<dim3(2, 24, 24), 256>>>(dt_w, dtw_h, dtw_l, 24, 768, 768, 64);

    // ---- patch embedding ----
    im2col_kernel<<<(MROWS * 768 + 255) / 256, 256>>>(images);
    mma_gemm<128,3,false,false,false><<<dim3(3, MT, 1), 256, SM_A1B1_128>>>(
        im_h, nullptr, 768, 0,  pw_h, nullptr, 768, 0,
        x, DM, 0, DM,  768/64,  patch_b, 0, pos_emb, nullptr, nullptr);

    for (int layer = 0; layer < DEPTH; layer++) {
        ln_kernel<<<MROWS, 128>>>(x, xn_h,
                                  ln_g + (size_t)layer * DM, ln_b + (size_t)layer * DM);

        // xz[dir] = xn @ in_w^T
        mma_gemm<128,0,false,false,false><<<dim3(12, MT, 2), 256, SM_A1B1_128>>>(
            xn_h, nullptr, DM, 0,
            inw_h + (size_t)layer * 2 * 2*DI * DM, nullptr, DM, (long)2*DI * DM,
            xz, 2*DI, (long)MROWS * 2*DI, 2*DI,
            DM/64, nullptr, 0, nullptr, nullptr, nullptr);

        conv_silu<<<(2 * MROWS * (DI/4) + 255) / 256, 256>>>(
            xz, conv_w + (size_t)layer * 2 * DI * 4, conv_b + (size_t)layer * 2 * DI,
            u_h, u_l);

        // dbc = u @ xproj_w  (split A and B: scan-critical)
        mma_gemm<64,0,true,true,true><<<dim3(1, MT, 2), 256, SM_A2B2_64>>>(
            u_h, u_l, DI, (long)MROWS * DI,
            xpw_h + (size_t)layer * 2 * 64 * DI,
            xpw_l + (size_t)layer * 2 * 64 * DI, DI, (long)64 * DI,
            dbcv, DBCN, (long)MROWS * DBCN, DBCN,
            DI/64, nullptr, 0, nullptr, dbch, dbcl);

        // dt = softplus(dbc[:, :24] @ dt_w + dt_b) — M-looped, B loaded once
        dt_gemm<<<dim3(6, 13, 2), 256, SM_DT>>>(
            dbch, dbcl,
            dtw_h + (size_t)layer * 2 * DI * 64,
            dtw_l + (size_t)layer * 2 * DI * 64,
            dtv, dt_b + (size_t)layer * 2 * DI);

        scan_kernel<<<dim3(6, BATCHN, 2), 128>>>(
            dtv, u_h, u_l, dbcv, xz,
            A_log + (size_t)layer * 2 * DI * DS, Dp + (size_t)layer * 2 * DI,
            y_h);

        // x += y @ out_w
        mma_gemm<128,2,false,false,false><<<dim3(3, MT, 1), 256, SM_A1B1_128>>>(
            y_h, nullptr, 2*DI, 0,
            outw_h + (size_t)layer * DM * 2*DI, nullptr, 2*DI, 0,
            x, DM, 0, DM,
            2*DI/64, nullptr, 0, x, nullptr, nullptr);
    }

    // final LN (fp32, into xz scratch) + pool + heads
    ln_f32<<<MROWS, 128>>>(x, xz, fln_g, fln_b);
    pool_head<<<BATCHN, 384>>>(xz, hdev_w, hdev_b, hdist_w, hdist_b, out);
    (void)in_sizes; (void)n_in; (void)out_size;
}

// round 16
// speedup vs baseline: 1.0623x; 1.0623x over previous
#include <cuda_runtime.h>
#include <cuda_fp16.h>
#include <math.h>
#include <stdint.h>

#define BATCHN 32
#define LSEQ   196
#define DM     384
#define DI     768
#define DS     16
#define DTR    24
#define DBCN   56
#define DEPTH  12
#define MROWS  (BATCHN*LSEQ)   // 6272

#if defined(__CUDA_ARCH__) && (defined(__CUDA_ARCH_FEAT_SM103_ALL) || defined(__CUDA_ARCH_SPECIFIC__))
#define HAS_TC 1
#else
#define HAS_TC 0
#endif

typedef __half f16;

// ---------------- scratch ----------------
__device__ __align__(256) float g_x  [MROWS*DM];
__device__ __align__(256) float g_xz [2*MROWS*2*DI];      // also reused as final-LN scratch
__device__ __align__(256) float g_dbc[2*MROWS*DBCN];
__device__ __align__(256) float g_dt [2*MROWS*DI];

__device__ __align__(256) f16 g_xn_h[MROWS*DM];
__device__ __align__(256) f16 g_im_h[MROWS*768];
__device__ __align__(256) f16 g_u_h [2*MROWS*DI],  g_u_l [2*MROWS*DI];
__device__ __align__(256) f16 g_y_h [MROWS*2*DI];
__device__ __align__(256) f16 g_dbch[2*MROWS*DBCN + 128], g_dbcl[2*MROWS*DBCN + 128];
__device__ __align__(256) f16 g_inw_h [DEPTH*2*2*DI*DM];
__device__ __align__(256) f16 g_outw_h[DEPTH*DM*2*DI];
__device__ __align__(256) f16 g_xpw_h [DEPTH*2*64*DI],   g_xpw_l [DEPTH*2*64*DI];
__device__ __align__(256) f16 g_dtw_h [DEPTH*2*DI*64],   g_dtw_l [DEPTH*2*DI*64]; // cols>=24 zero
__device__ __align__(256) f16 g_pw_h  [DM*768];

__device__ __forceinline__ void split2(float v, f16& h, f16& l) {
    h = __float2half_rn(v);
    l = __float2half_rn(v - __half2float(h));
}

#if HAS_TC
__device__ __forceinline__ uint32_t smem_u32(const void* p) {
    uint32_t a;
    asm("{ .reg .u64 t; cvta.to.shared.u64 t, %1; cvt.u32.u64 %0, t; }" : "=r"(a) : "l"(p));
    return a;
}
__device__ __forceinline__ uint32_t elect_one() {
    uint32_t p;
    asm volatile("{ .reg .pred p; elect.sync _|p, 0xFFFFFFFF; selp.b32 %0,1,0,p; }" : "=r"(p));
    return p;
}
#define SWZ(o) ((o) ^ (((o) >> 3) & 0x70))

static __device__ __forceinline__ uint64_t make_desc(uint32_t addr) {
    const uint64_t base =
        (uint64_t(2) << 61) | (uint64_t(1) << 46) | (uint64_t(64) << 32) | (uint64_t(1) << 16);
    return base | ((uint64_t)(addr >> 4) & 0x3FFF);
}

#define MBAR_INIT(a, c) \
    asm volatile("mbarrier.init.shared.b64 [%0], %1;" :: "r"(a), "r"(c) : "memory")
#define MBAR_INVAL(a) \
    asm volatile("mbarrier.inval.shared.b64 [%0];" :: "r"(a) : "memory")
#define MBAR_WAIT(a, ph) do {                                            \
    uint32_t _m = (a); uint32_t _p = (ph); uint32_t _d;                  \
    asm volatile("{ .reg .pred p; mbarrier.try_wait.parity.acquire.cta.shared::cta.b64 p,[%1],%2; selp.b32 %0,1,0,p; }" \
        : "=r"(_d) : "r"(_m), "r"(_p) : "memory");                       \
    if (!_d) {                                                           \
        asm volatile("{ .reg .pred P1; W%=: mbarrier.try_wait.parity.acquire.cta.shared::cta.b64 P1,[%0],%1,0x989680; @P1 bra.uni D%=; bra.uni W%=; D%=: }" \
            :: "r"(_m), "r"(_p) : "memory");                             \
    } } while (0)

#define CP_ASYNC16(dst, src) \
    asm volatile("cp.async.cg.shared.global [%0], [%1], 16;" :: "r"(dst), "l"(src) : "memory")
#define CP_COMMIT() asm volatile("cp.async.commit_group;" ::: "memory")
#define CP_WAIT1()  asm volatile("cp.async.wait_group 1;" ::: "memory")

__device__ __forceinline__ void tc_alloc(uint32_t smem_dst, uint32_t ncols) {
    asm volatile("tcgen05.alloc.cta_group::1.sync.aligned.shared::cta.b32 [%0], %1;"
                 :: "r"(smem_dst), "r"(ncols) : "memory");
}
__device__ __forceinline__ void tc_relinq() {
    asm volatile("tcgen05.relinquish_alloc_permit.cta_group::1.sync.aligned;");
}
__device__ __forceinline__ void tc_dealloc(uint32_t tmem, uint32_t ncols) {
    asm volatile("tcgen05.dealloc.cta_group::1.sync.aligned.b32 %0, %1;" :: "r"(tmem), "r"(ncols));
}
__device__ __forceinline__ void tc_commit(uint32_t mbar) {
    asm volatile("tcgen05.commit.cta_group::1.mbarrier::arrive::one.shared::cluster.b64 [%0];"
                 :: "r"(mbar) : "memory");
}
__device__ __forceinline__ void mma_f16(uint32_t d, uint64_t ad, uint64_t bd, uint32_t idesc, bool acc) {
    uint32_t en = acc ? 1u : 0u, z = 0u;
    asm volatile(
        "{ .reg .pred p; setp.ne.u32 p, %5, 0;"
        " tcgen05.mma.cta_group::1.kind::f16 [%0], %1, %2, %3, {%4,%4,%4,%4}, p; }"
        :: "r"(d), "l"(ad), "l"(bd), "r"(idesc), "r"(z), "r"(en) : "memory");
}
#define TC_LD_X32(r, a)                                                     \
    asm volatile("tcgen05.ld.sync.aligned.32x32b.x32.b32 "                  \
        "{%0,%1,%2,%3,%4,%5,%6,%7,%8,%9,%10,%11,%12,%13,%14,%15,"           \
        "%16,%17,%18,%19,%20,%21,%22,%23,%24,%25,%26,%27,%28,%29,%30,%31}, [%32];" \
        : "=r"((r)[0]),"=r"((r)[1]),"=r"((r)[2]),"=r"((r)[3]),"=r"((r)[4]),"=r"((r)[5]),"=r"((r)[6]),"=r"((r)[7]), \
          "=r"((r)[8]),"=r"((r)[9]),"=r"((r)[10]),"=r"((r)[11]),"=r"((r)[12]),"=r"((r)[13]),"=r"((r)[14]),"=r"((r)[15]), \
          "=r"((r)[16]),"=r"((r)[17]),"=r"((r)[18]),"=r"((r)[19]),"=r"((r)[20]),"=r"((r)[21]),"=r"((r)[22]),"=r"((r)[23]), \
          "=r"((r)[24]),"=r"((r)[25]),"=r"((r)[26]),"=r"((r)[27]),"=r"((r)[28]),"=r"((r)[29]),"=r"((r)[30]),"=r"((r)[31]) \
        : "r"(a))
#define TC_WAIT_LD() asm volatile("tcgen05.wait::ld.sync.aligned;" ::: "memory")
#define TC_FENCE_AFTER() asm volatile("tcgen05.fence::after_thread_sync;" ::: "memory")

// ---- packed f32x2 helpers (sm_103a) ----
__device__ __forceinline__ uint64_t pk2(float lo, float hi) {
    uint64_t r; asm("mov.b64 %0, {%1, %2};" : "=l"(r) : "f"(lo), "f"(hi)); return r;
}
__device__ __forceinline__ void upk2(uint64_t v, float& lo, float& hi) {
    asm("mov.b64 {%0, %1}, %2;" : "=f"(lo), "=f"(hi) : "l"(v));
}
__device__ __forceinline__ uint64_t mul2(uint64_t a, uint64_t b) {
    uint64_t r; asm("mul.rn.f32x2 %0, %1, %2;" : "=l"(r) : "l"(a), "l"(b)); return r;
}
__device__ __forceinline__ uint64_t fma2(uint64_t a, uint64_t b, uint64_t c) {
    uint64_t r; asm("fma.rn.f32x2 %0, %1, %2, %3;" : "=l"(r) : "l"(a), "l"(b), "l"(c)); return r;
}
#endif  // HAS_TC

__device__ __forceinline__ float softplusf(float v) {
    return (v > 0.f) ? v + log1pf(__expf(-v)) : log1pf(__expf(v));
}

// =====================================================================
// fp16 tcgen05 GEMM, 3-stage cp.async ring, 256 threads (R13-proven).
// C = (Ah[+Al]) @ ((Bh[+Bl])^T  in fp32 accum.
// MMA groups: AhBh [+ AlBh if ASPLIT] [+ AhBl if BSPLIT].
// K-step = 64 elements. S = K/64. Only min(S,3) stages touched ->
// launch smem may be sized as 1024 + min(S,3)*STAGE.
// EPI: 0 plain, 1 softplus(v+bias), 2 v+res, 3 v+bias+res[(m%L)*ldc+col]
// =====================================================================
template<int NT, int EPI, bool ASPLIT, bool BSPLIT, bool SPLITOUT>
__global__ void __launch_bounds__(256) mma_gemm(
    const f16* __restrict__ Ah, const f16* __restrict__ Al, int lda, long sA,
    const f16* __restrict__ Bh, const f16* __restrict__ Bl, int ldb, long sB,
    float* __restrict__ C, int ldc, long sC, int Ncols,
    int S,
    const float* __restrict__ bias, long sBias,
    const float* __restrict__ res,
    f16* __restrict__ Ch, f16* __restrict__ Cl)
{
    const int tid = threadIdx.x;
    const int m0 = blockIdx.y * 128, n0 = blockIdx.x * NT;
    Ah += (size_t)blockIdx.z * sA;
    if (ASPLIT) Al += (size_t)blockIdx.z * sA;
    Bh += (size_t)blockIdx.z * sB;
    if (BSPLIT) Bl += (size_t)blockIdx.z * sB;
    C  += (size_t)blockIdx.z * sC;
    if (bias) bias += (size_t)blockIdx.z * sBias;
    if (SPLITOUT) { Ch += (size_t)blockIdx.z * sC; Cl += (size_t)blockIdx.z * sC; }

#if HAS_TC
    extern __shared__ char smem[];
    const uint32_t sb = smem_u32(smem);
    const int wid = tid >> 5, lane = tid & 31;
    constexpr int ABYTES = 128 * 128;
    constexpr int BBYTES = NT * 128;
    constexpr int NA     = ASPLIT ? 2 : 1;
    constexpr int NB     = BSPLIT ? 2 : 1;
    constexpr int STAGE  = NA * ABYTES + NB * BBYTES;

    if (tid == 0) {
#pragma unroll
        for (int i = 0; i < 3; i++) MBAR_INIT(sb + 8 + i * 8, 1);
    }
    if (wid == 0) { tc_alloc(sb, NT); tc_relinq(); }
    __syncthreads();
    uint32_t tmem;
    asm volatile("ld.shared.b32 %0, [%1];" : "=r"(tmem) : "r"(sb));

    const uint32_t idesc = 0x10u | ((uint32_t)(NT / 8) << 17) | (8u << 24);

    auto stage_load = [&](int r, int step) {
        const int k0 = step << 6;
        const uint32_t ah = sb + 1024 + r * STAGE;
        const uint32_t al = ah + ABYTES;
        const uint32_t bh = ah + NA * ABYTES;
        const uint32_t bl = bh + BBYTES;
#pragma unroll
        for (int i = 0; i < 4; i++) {
            int c = i * 256 + tid; int row = c >> 3, q = c & 7;
            uint32_t so = SWZ(row * 128 + q * 16);
            size_t go = (size_t)(m0 + row) * lda + k0 + q * 8;
            CP_ASYNC16(ah + so, Ah + go);
            if (ASPLIT) CP_ASYNC16(al + so, Al + go);
        }
#pragma unroll
        for (int i = 0; i < NT / 32; i++) {
            int c = i * 256 + tid; int row = c >> 3, q = c & 7;
            uint32_t so = SWZ(row * 128 + q * 16);
            size_t go = (size_t)(n0 + row) * ldb + k0 + q * 8;
            CP_ASYNC16(bh + so, Bh + go);
            if (BSPLIT) CP_ASYNC16(bl + so, Bl + go);
        }
    };

#pragma unroll
    for (int p = 0; p < 3; p++) { if (p < S) stage_load(p, p); CP_COMMIT(); }

    int ph[3] = {0, 0, 0};
    for (int s = 0; s < S; s++) {
        CP_WAIT1();
        asm volatile("fence.proxy.async.shared::cta;" ::: "memory");
        __syncthreads();
        const int st = s % 3;
        if (wid == 0 && elect_one()) {
            const uint32_t ah = sb + 1024 + st * STAGE;
            uint64_t adh = make_desc(ah);
            uint64_t bdh = make_desc(ah + NA * ABYTES);
#pragma unroll
            for (int sl = 0; sl < 4; sl++)
                mma_f16(tmem, adh + sl * 2, bdh + sl * 2, idesc, (s > 0) || (sl > 0));
            if (ASPLIT) {
                uint64_t adl = make_desc(ah + ABYTES);
#pragma unroll
                for (int sl = 0; sl < 4; sl++)
                    mma_f16(tmem, adl + sl * 2, bdh + sl * 2, idesc, true);
            }
            if (BSPLIT) {
                uint64_t bdl = make_desc(ah + NA * ABYTES + BBYTES);
#pragma unroll
                for (int sl = 0; sl < 4; sl++)
                    mma_f16(tmem, adh + sl * 2, bdl + sl * 2, idesc, true);
            }
            tc_commit(sb + 8 + st * 8);
        }
        if (s >= 1 && s + 2 < S) {
            const int r = (s + 2) % 3;
            MBAR_WAIT(sb + 8 + r * 8, ph[r]); ph[r] ^= 1;
            stage_load(r, s + 2);
        }
        CP_COMMIT();
    }
    MBAR_WAIT(sb + 8 + ((S - 1) % 3) * 8, ph[(S - 1) % 3]);
    TC_FENCE_AFTER();

    const int subp = wid & 3, half = wid >> 2;
#pragma unroll
    for (int ch = 0; ch < NT / 64; ch++) {
        const int chunk = half * (NT / 64) + ch;
        uint32_t r[32];
        TC_LD_X32(r, tmem + chunk * 32);
        TC_WAIT_LD();
        const int row = m0 + subp * 32 + lane;
        const int col0 = n0 + chunk * 32;
        float* cp = C + (size_t)row * ldc + col0;
        float vals[32];
#pragma unroll
        for (int j = 0; j < 32; j++) {
            float v = __uint_as_float(r[j]);
            const int col = col0 + j;
            if (EPI == 1) v = softplusf(v + bias[col]);
            if (EPI == 2) v += res[(size_t)row * ldc + col];
            if (EPI == 3) v += bias[col] + res[(size_t)(row % LSEQ) * ldc + col];
            vals[j] = v;
        }
        if (col0 + 31 < Ncols) {
#pragma unroll
            for (int g = 0; g < 8; g++)
                *(float4*)(cp + g * 4) =
                    make_float4(vals[4*g], vals[4*g+1], vals[4*g+2], vals[4*g+3]);
            if (SPLITOUT) {
#pragma unroll
                for (int j = 0; j < 32; j++) {
                    f16 hh, ll; split2(vals[j], hh, ll);
                    Ch[(size_t)row * ldc + col0 + j] = hh;
                    Cl[(size_t)row * ldc + col0 + j] = ll;
                }
            }
        } else {
#pragma unroll
            for (int j = 0; j < 32; j++)
                if (col0 + j < Ncols) {
                    cp[j] = vals[j];
                    if (SPLITOUT) {
                        f16 hh, ll; split2(vals[j], hh, ll);
                        Ch[(size_t)row * ldc + col0 + j] = hh;
                        Cl[(size_t)row * ldc + col0 + j] = ll;
                    }
                }
        }
    }
    __syncthreads();
    if (tid == 0) {
#pragma unroll
        for (int i = 0; i < 3; i++) MBAR_INVAL(sb + 8 + i * 8);
    }
    if (wid == 0) tc_dealloc(tmem, NT);
#else
    if (tid >= 128) return;
    const int row = m0 + tid;
    const int K = S * 64;
    for (int n = 0; n < NT; n++) {
        const int col = n0 + n;
        if (col >= Ncols) break;
        float acc = 0.f;
        for (int k = 0; k < K; k++) {
            float a = __half2float(Ah[(size_t)row * lda + k]);
            if (ASPLIT) a += __half2float(Al[(size_t)row * lda + k]);
            float b = __half2float(Bh[(size_t)col * ldb + k]);
            if (BSPLIT) b += __half2float(Bl[(size_t)col * ldb + k]);
            acc = fmaf(a, b, acc);
        }
        float v = acc;
        if (EPI == 1) v = softplusf(v + bias[col]);
        if (EPI == 2) v += res[(size_t)row * ldc + col];
        if (EPI == 3) v += bias[col] + res[(size_t)(row % LSEQ) * ldc + col];
        C[(size_t)row * ldc + col] = v;
        if (SPLITOUT) {
            f16 hh, ll; split2(v, hh, ll);
            Ch[(size_t)row * ldc + col] = hh;
            Cl[(size_t)row * ldc + col] = ll;
        }
    }
#endif
}

// ---- transpose + zero-pad + fp16-split (two planes) ----
__global__ void __launch_bounds__(256) transpose_split(
    const float* __restrict__ in, f16* __restrict__ oh, f16* __restrict__ ol,
    int R, int C, int OR_, int OC)
{
    __shared__ float t[32][33];
    const int z = blockIdx.z;
    in += (size_t)z * R * C;
    oh += (size_t)z * OR_ * OC;
    ol += (size_t)z * OR_ * OC;
    const int j0 = blockIdx.x * 32;
    const int i0 = blockIdx.y * 32;
    const int tx = threadIdx.x & 31, ty = threadIdx.x >> 5;
#pragma unroll
    for (int k = 0; k < 4; k++) {
        int rin = j0 + ty + k * 8, cin = i0 + tx;
        t[ty + k * 8][tx] = (rin < R && cin < C) ? in[(size_t)rin * C + cin] : 0.f;
    }
    __syncthreads();
#pragma unroll
    for (int k = 0; k < 4; k++) {
        int orow = i0 + ty + k * 8, ocol = j0 + tx;
        if (orow < OR_ && ocol < OC) {
            f16 h, l; split2(t[tx][ty + k * 8], h, l);
            oh[(size_t)orow * OC + ocol] = h;
            ol[(size_t)orow * OC + ocol] = l;
        }
    }
}

// ---- transpose + fp16 single plane ----
__global__ void __launch_bounds__(256) transpose_h(
    const float* __restrict__ in, f16* __restrict__ oh, int R, int C)
{
    __shared__ float t[32][33];
    const int z = blockIdx.z;
    in += (size_t)z * R * C;
    oh += (size_t)z * R * C;
    const int j0 = blockIdx.x * 32;
    const int i0 = blockIdx.y * 32;
    const int tx = threadIdx.x & 31, ty = threadIdx.x >> 5;
#pragma unroll
    for (int k = 0; k < 4; k++)
        t[ty + k * 8][tx] = in[(size_t)(j0 + ty + k * 8) * C + i0 + tx];
    __syncthreads();
#pragma unroll
    for (int k = 0; k < 4; k++)
        oh[(size_t)(i0 + ty + k * 8) * R + j0 + tx] = __float2half_rn(t[tx][ty + k * 8]);
}

__global__ void half_copy(const float* __restrict__ in, f16* __restrict__ oh, int n)
{
    int i = blockIdx.x * blockDim.x + threadIdx.x;
    if (i < n) oh[i] = __float2half_rn(in[i]);
}

// ---------------- LayerNorm -> fp16 single ----------------
__global__ void __launch_bounds__(128) ln_kernel(
    const float* __restrict__ x, f16* __restrict__ yh,
    const float* __restrict__ g, const float* __restrict__ b)
{
    const int row = blockIdx.x;
    const int tid = threadIdx.x;
    const float* xr = x + (size_t)row * DM;
    float v0 = xr[tid], v1 = xr[tid + 128], v2 = xr[tid + 256];
    __shared__ float sh[4];
    float s = v0 + v1 + v2;
#pragma unroll
    for (int o = 16; o > 0; o >>= 1) s += __shfl_xor_sync(0xffffffffu, s, o);
    if ((tid & 31) == 0) sh[tid >> 5] = s;
    __syncthreads();
    float mu = (sh[0] + sh[1] + sh[2] + sh[3]) * (1.f / DM);
    float d0 = v0 - mu, d1 = v1 - mu, d2 = v2 - mu;
    float q = d0*d0 + d1*d1 + d2*d2;
    __syncthreads();
#pragma unroll
    for (int o = 16; o > 0; o >>= 1) q += __shfl_xor_sync(0xffffffffu, q, o);
    if ((tid & 31) == 0) sh[tid >> 5] = q;
    __syncthreads();
    float var = (sh[0] + sh[1] + sh[2] + sh[3]) * (1.f / DM);
    float rs = rsqrtf(var + 1e-5f);
    size_t base = (size_t)row * DM;
    yh[base + tid]       = __float2half_rn(d0 * rs * g[tid]       + b[tid]);
    yh[base + tid + 128] = __float2half_rn(d1 * rs * g[tid + 128] + b[tid + 128]);
    yh[base + tid + 256] = __float2half_rn(d2 * rs * g[tid + 256] + b[tid + 256]);
}

// ---------------- final LayerNorm -> fp32 ----------------
__global__ void __launch_bounds__(128) ln_f32(
    const float* __restrict__ x, float* __restrict__ y,
    const float* __restrict__ g, const float* __restrict__ b)
{
    const int row = blockIdx.x;
    const int tid = threadIdx.x;
    const float* xr = x + (size_t)row * DM;
    float v0 = xr[tid], v1 = xr[tid + 128], v2 = xr[tid + 256];
    __shared__ float sh[4];
    float s = v0 + v1 + v2;
#pragma unroll
    for (int o = 16; o > 0; o >>= 1) s += __shfl_xor_sync(0xffffffffu, s, o);
    if ((tid & 31) == 0) sh[tid >> 5] = s;
    __syncthreads();
    float mu = (sh[0] + sh[1] + sh[2] + sh[3]) * (1.f / DM);
    float d0 = v0 - mu, d1 = v1 - mu, d2 = v2 - mu;
    float q = d0*d0 + d1*d1 + d2*d2;
    __syncthreads();
#pragma unroll
    for (int o = 16; o > 0; o >>= 1) q += __shfl_xor_sync(0xffffffffu, q, o);
    if ((tid & 31) == 0) sh[tid >> 5] = q;
    __syncthreads();
    float var = (sh[0] + sh[1] + sh[2] + sh[3]) * (1.f / DM);
    float rs = rsqrtf(var + 1e-5f);
    float* yr = y + (size_t)row * DM;
    yr[tid]       = d0 * rs * g[tid]       + b[tid];
    yr[tid + 128] = d1 * rs * g[tid + 128] + b[tid + 128];
    yr[tid + 256] = d2 * rs * g[tid + 256] + b[tid + 256];
}

// ---------------- conv1d + SiLU, 4 channels/thread (R11-proven) ----------------
__global__ void conv_silu(const float* __restrict__ xz, const float* __restrict__ w,
                          const float* __restrict__ bias,
                          f16* __restrict__ uh, f16* __restrict__ ul)
{
    const int CQ = DI / 4;
    int idx = blockIdx.x * blockDim.x + threadIdx.x;
    if (idx >= 2 * MROWS * CQ) return;
    int q   = idx % CQ;  int c4 = q * 4;
    int m   = (idx / CQ) % MROWS;
    int dir = idx / (CQ * MROWS);
    int l = m % LSEQ, mbase = m - l;
    const float* xzd = xz + (size_t)dir * MROWS * 2 * DI;
    const float* wp = w + (size_t)dir * DI * 4 + c4 * 4;
    float4 w0 = *(const float4*)(wp);
    float4 w1 = *(const float4*)(wp + 4);
    float4 w2 = *(const float4*)(wp + 8);
    float4 w3 = *(const float4*)(wp + 12);
    float4 bv = *(const float4*)(bias + dir * DI + c4);
    float a0 = bv.x, a1 = bv.y, a2 = bv.z, a3 = bv.w;
    const float wk0[4] = {w0.x, w0.y, w0.z, w0.w};
    const float wk1[4] = {w1.x, w1.y, w1.z, w1.w};
    const float wk2[4] = {w2.x, w2.y, w2.z, w2.w};
    const float wk3[4] = {w3.x, w3.y, w3.z, w3.w};
#pragma unroll
    for (int k = 0; k < 4; k++) {
        int ls = dir ? (l + 3 - k) : (l - 3 + k);
        if (ls >= 0 && ls < LSEQ) {
            float4 xv = *(const float4*)(xzd + (size_t)(mbase + ls) * 2 * DI + c4);
            a0 = fmaf(wk0[k], xv.x, a0);
            a1 = fmaf(wk1[k], xv.y, a1);
            a2 = fmaf(wk2[k], xv.z, a2);
            a3 = fmaf(wk3[k], xv.w, a3);
        }
    }
    float u0 = a0 / (1.f + __expf(-a0));
    float u1 = a1 / (1.f + __expf(-a1));
    float u2 = a2 / (1.f + __expf(-a2));
    float u3 = a3 / (1.f + __expf(-a3));
    size_t o = (size_t)dir * MROWS * DI + (size_t)m * DI + c4;
    f16 h0,l0,h1,l1,h2,l2,h3,l3;
    split2(u0,h0,l0); split2(u1,h1,l1); split2(u2,h2,l2); split2(u3,h3,l3);
    __half2* uhp = (__half2*)(uh + o);
    __half2* ulp = (__half2*)(ul + o);
    uhp[0] = __halves2half2(h0, h1);
    uhp[1] = __halves2half2(h2, h3);
    ulp[0] = __halves2half2(l0, l1);
    ulp[1] = __halves2half2(l2, l3);
}

// ---------------- selective scan (packed f32x2 fast path) -> y fp16 ----------------
__global__ void __launch_bounds__(128) scan_kernel(
    const float* __restrict__ dt,
    const f16* __restrict__ uh, const f16* __restrict__ ul,
    const float* __restrict__ dbc, const float* __restrict__ xz,
    const float* __restrict__ A_log, const float* __restrict__ Dp,
    f16* __restrict__ yh)
{
    const int c   = blockIdx.x * 128 + threadIdx.x;
    const int b   = blockIdx.y;
    const int dir = blockIdx.z;

    __shared__ __align__(16) float Bsh[LSEQ][DS];
    __shared__ __align__(16) float Csh[LSEQ][DS];
    const float* dbcb = dbc + ((size_t)dir * MROWS + (size_t)b * LSEQ) * DBCN;
    for (int i = threadIdx.x; i < LSEQ * 2 * DS; i += 128) {
        int l = i >> 5, j = i & 31;
        float v = dbcb[(size_t)l * DBCN + DTR + j];
        if (j < DS) Bsh[l][j] = v; else Csh[l][j - DS] = v;
    }
    __syncthreads();

    float a[DS];
    const float* ap = A_log + ((size_t)dir * DI + c) * DS;
#pragma unroll
    for (int n = 0; n < DS; n++) a[n] = -__expf(ap[n]);
    const float a0 = a[0];
    bool fast = true;
#pragma unroll
    for (int n = 1; n < DS; n++)
        fast = fast && (fabsf(a[n] - a0 * (float)(n + 1)) <= 1e-4f * fabsf(a[n]));
    const float dp = Dp[dir * DI + c];

    const size_t ubase = ((size_t)dir * MROWS + (size_t)b * LSEQ) * DI + c;
    const float* dtb = dt + ubase;
    const float* zb  = xz + ((size_t)dir * MROWS + (size_t)b * LSEQ) * 2 * DI + DI + c;
    const size_t ybase = ((size_t)b * LSEQ) * 2 * DI + (size_t)dir * DI + c;

    int l = dir ? (LSEQ - 1) : 0;
    float dt_n = dtb[(size_t)l * DI];
    float uh_n = __half2float(uh[ubase + (size_t)l * DI]);
    float ul_n = __half2float(ul[ubase + (size_t)l * DI]);
    float z_n  = zb[(size_t)l * 2 * DI];

#if HAS_TC
    if (fast) {
        uint64_t h2[8];
#pragma unroll
        for (int k = 0; k < 8; k++) h2[k] = 0ull;
        for (int t = 0; t < LSEQ; t++) {
            const int lc = l;
            const float dtv = dt_n;
            const float uv  = uh_n + ul_n;
            const float zv  = z_n;
            if (t + 1 < LSEQ) {
                l = dir ? (LSEQ - 2 - t) : (t + 1);
                dt_n = dtb[(size_t)l * DI];
                uh_n = __half2float(uh[ubase + (size_t)l * DI]);
                ul_n = __half2float(ul[ubase + (size_t)l * DI]);
                z_n  = zb[(size_t)l * 2 * DI];
            }
            const float du = dtv * uv;
            const float e1 = __expf(dtv * a0);
            const float e2 = e1 * e1;
            const uint64_t E2  = pk2(e2, e2);
            const uint64_t du2 = pk2(du, du);
            uint64_t p = pk2(e1, e2);
            uint64_t acc2 = pk2(0.f, 0.f);
            const uint64_t* B2 = (const uint64_t*)&Bsh[lc][0];
            const uint64_t* C2 = (const uint64_t*)&Csh[lc][0];
#pragma unroll
            for (int k = 0; k < 8; k++) {
                if (k > 0) p = mul2(p, E2);
                uint64_t tmp = mul2(du2, B2[k]);
                h2[k] = fma2(p, h2[k], tmp);
                acc2 = fma2(h2[k], C2[k], acc2);
            }
            float alo, ahi; upk2(acc2, alo, ahi);
            const float yv = alo + ahi + dp * uv;
            const float og = yv * (zv / (1.f + __expf(-zv)));
            yh[ybase + (size_t)lc * 2 * DI] = __float2half_rn(og);
        }
        return;
    }
#endif
    float h[DS];
#pragma unroll
    for (int n = 0; n < DS; n++) h[n] = 0.f;
    for (int t = 0; t < LSEQ; t++) {
        const int lc = l;
        const float dtv = dt_n;
        const float uv  = uh_n + ul_n;
        const float zv  = z_n;
        if (t + 1 < LSEQ) {
            l = dir ? (LSEQ - 2 - t) : (t + 1);
            dt_n = dtb[(size_t)l * DI];
            uh_n = __half2float(uh[ubase + (size_t)l * DI]);
            ul_n = __half2float(ul[ubase + (size_t)l * DI]);
            z_n  = zb[(size_t)l * 2 * DI];
        }
        const float du = dtv * uv;
        float acc = 0.f;
        if (fast) {
            const float e1 = __expf(dtv * a0);
            float p = 1.f;
#pragma unroll
            for (int n = 0; n < DS; n++) {
                p *= e1;
                h[n] = p * h[n] + du * Bsh[lc][n];
                acc = fmaf(h[n], Csh[lc][n], acc);
            }
        } else {
#pragma unroll
            for (int n = 0; n < DS; n++) {
                h[n] = __expf(dtv * a[n]) * h[n] + du * Bsh[lc][n];
                acc = fmaf(h[n], Csh[lc][n], acc);
            }
        }
        const float yv = acc + dp * uv;
        const float og = yv * (zv / (1.f + __expf(-zv)));
        yh[ybase + (size_t)lc * 2 * DI] = __float2half_rn(og);
    }
}

// ---------------- pool + heads (after ln_f32) ----------------
__global__ void __launch_bounds__(384) pool_head(
    const float* __restrict__ fln,
    const float* __restrict__ wdev, const float* __restrict__ bdev,
    const float* __restrict__ wdist, const float* __restrict__ bdist,
    float* __restrict__ out)
{
    const int b = blockIdx.x;
    const int tid = threadIdx.x;
    __shared__ float pooled_s[DM];
    float s = 0.f;
    for (int l = 0; l < LSEQ; l++)
        s += fln[((size_t)b * LSEQ + l) * DM + tid];
    pooled_s[tid] = s * (1.f / LSEQ);
    __syncthreads();
    if (tid < 7) {
        float acc = bdev[tid];
        for (int d = 0; d < DM; d++) acc += pooled_s[d] * wdev[d * 7 + tid];
        out[b * 7 + tid] = acc;
    } else if (tid < 11) {
        int j = tid - 7;
        float acc = bdist[j];
        for (int d = 0; d < DM; d++) acc += pooled_s[d] * wdist[d * 4 + j];
        out[BATCHN * 7 + b * 4 + j] = acc;
    }
}

// ---------------- im2col -> fp16 single ----------------
__global__ void im2col_kernel(const float* __restrict__ img)
{
    int idx = blockIdx.x * blockDim.x + threadIdx.x;
    if (idx >= MROWS * 768) return;
    int k = idx % 768;
    int m = idx / 768;
    int b = m / LSEQ, l = m % LSEQ;
    int ph = l / 14, pw = l % 14;
    int ch  = k >> 8;
    int r   = (k >> 4) & 15;
    int col = k & 15;
    float v = img[(((size_t)b * 3 + ch) * 224 + ph * 16 + r) * 224 + pw * 16 + col];
    g_im_h[idx] = __float2half_rn(v);
}

// ---------------- launcher ----------------
extern "C" void kernel_launch(void* const* d_in, const int* in_sizes, int n_in,
                              void* d_out, int out_size)
{
    const float* images  = (const float*)d_in[0];
    const float* patch_w = (const float*)d_in[1];
    const float* patch_b = (const float*)d_in[2];
    const float* pos_emb = (const float*)d_in[3];
    const float* ln_g    = (const float*)d_in[4];
    const float* ln_b    = (const float*)d_in[5];
    const float* in_w    = (const float*)d_in[6];
    const float* conv_w  = (const float*)d_in[7];
    const float* conv_b  = (const float*)d_in[8];
    const float* xproj_w = (const float*)d_in[9];
    const float* dt_w    = (const float*)d_in[10];
    const float* dt_b    = (const float*)d_in[11];
    const float* A_log   = (const float*)d_in[12];
    const float* Dp      = (const float*)d_in[13];
    const float* out_w   = (const float*)d_in[14];
    const float* fln_g   = (const float*)d_in[15];
    const float* fln_b   = (const float*)d_in[16];
    const float* hdev_w  = (const float*)d_in[17];
    const float* hdev_b  = (const float*)d_in[18];
    const float* hdist_w = (const float*)d_in[19];
    const float* hdist_b = (const float*)d_in[20];
    float* out = (float*)d_out;

    float *x, *xz, *dbcv, *dtv;
    f16 *xn_h, *im_h, *u_h, *u_l, *y_h, *dbch, *dbcl;
    f16 *inw_h, *outw_h, *xpw_h, *xpw_l, *dtw_h, *dtw_l, *pw_h;
    cudaGetSymbolAddress((void**)&x,     g_x);
    cudaGetSymbolAddress((void**)&xz,    g_xz);
    cudaGetSymbolAddress((void**)&dbcv,  g_dbc);
    cudaGetSymbolAddress((void**)&dtv,   g_dt);
    cudaGetSymbolAddress((void**)&xn_h,  g_xn_h);
    cudaGetSymbolAddress((void**)&im_h,  g_im_h);
    cudaGetSymbolAddress((void**)&u_h,   g_u_h);   cudaGetSymbolAddress((void**)&u_l,   g_u_l);
    cudaGetSymbolAddress((void**)&y_h,   g_y_h);
    cudaGetSymbolAddress((void**)&dbch,  g_dbch);  cudaGetSymbolAddress((void**)&dbcl,  g_dbcl);
    cudaGetSymbolAddress((void**)&inw_h, g_inw_h);
    cudaGetSymbolAddress((void**)&outw_h,g_outw_h);
    cudaGetSymbolAddress((void**)&xpw_h, g_xpw_h); cudaGetSymbolAddress((void**)&xpw_l, g_xpw_l);
    cudaGetSymbolAddress((void**)&dtw_h, g_dtw_h); cudaGetSymbolAddress((void**)&dtw_l, g_dtw_l);
    cudaGetSymbolAddress((void**)&pw_h,  g_pw_h);

    // smem: 1024 + nStages * STAGE (only min(S,3) stages are ever touched)
    const int SM_A1B1_128 = 1024 + 3 * (16384 + 16384);             // 99328  (2 CTAs/SM)
    const int SM_A2B2_64  = 1024 + 3 * (2 * 16384 + 2 * 64 * 128);  // 148480
    const int SM_A2B2_128_S1 = 1024 + 1 * (2 * 16384 + 2 * 128 * 128); // 66560 (3 CTAs/SM)
    cudaFuncSetAttribute(mma_gemm<128,0,false,false,false>, cudaFuncAttributeMaxDynamicSharedMemorySize, SM_A1B1_128);
    cudaFuncSetAttribute(mma_gemm<128,2,false,false,false>, cudaFuncAttributeMaxDynamicSharedMemorySize, SM_A1B1_128);
    cudaFuncSetAttribute(mma_gemm<128,3,false,false,false>, cudaFuncAttributeMaxDynamicSharedMemorySize, SM_A1B1_128);
    cudaFuncSetAttribute(mma_gemm<64,0,true,true,true>,     cudaFuncAttributeMaxDynamicSharedMemorySize, SM_A2B2_64);
    cudaFuncSetAttribute(mma_gemm<128,1,true,true,false>,   cudaFuncAttributeMaxDynamicSharedMemorySize, SM_A2B2_128_S1);

    const int MT = MROWS / 128;  // 49

    // ---- weight packing ----
    transpose_h<<<dim3(12, 48, 24), 256>>>(in_w, inw_h, 384, 1536);
    transpose_h<<<dim3(48, 12, 12), 256>>>(out_w, outw_h, 1536, 384);
    half_copy<<<(DM*768 + 255)/256, 256>>>(patch_w, pw_h, DM*768);
    transpose_split<<<dim3(24, 2, 24), 256>>>(xproj_w, xpw_h, xpw_l, 768, 56, 64, 768);
    transpose_split<<<dim3(2, 24, 24), 256>>>(dt_w, dtw_h, dtw_l, 24, 768, 768, 64);

    // ---- patch embedding ----
    im2col_kernel<<<(MROWS * 768 + 255) / 256, 256>>>(images);
    mma_gemm<128,3,false,false,false><<<dim3(3, MT, 1), 256, SM_A1B1_128>>>(
        im_h, nullptr, 768, 0,  pw_h, nullptr, 768, 0,
        x, DM, 0, DM,  768/64,  patch_b, 0, pos_emb, nullptr, nullptr);

    for (int layer = 0; layer < DEPTH; layer++) {
        ln_kernel<<<MROWS, 128>>>(x, xn_h,
                                  ln_g + (size_t)layer * DM, ln_b + (size_t)layer * DM);

        // xz[dir] = xn @ in_w^T  (single-plane A and B: 1 MMA group, 2 CTAs/SM)
        mma_gemm<128,0,false,false,false><<<dim3(12, MT, 2), 256, SM_A1B1_128>>>(
            xn_h, nullptr, DM, 0,
            inw_h + (size_t)layer * 2 * 2*DI * DM, nullptr, DM, (long)2*DI * DM,
            xz, 2*DI, (long)MROWS * 2*DI, 2*DI,
            DM/64, nullptr, 0, nullptr, nullptr, nullptr);

        // conv: 4 channels/thread (R11-proven parallel form)
        conv_silu<<<(2 * MROWS * (DI/4) + 255) / 256, 256>>>(
            xz, conv_w + (size_t)layer * 2 * DI * 4, conv_b + (size_t)layer * 2 * DI,
            u_h, u_l);

        // dbc = u @ xproj_w  (split A and B: scan-critical)
        mma_gemm<64,0,true,true,true><<<dim3(1, MT, 2), 256, SM_A2B2_64>>>(
            u_h, u_l, DI, (long)MROWS * DI,
            xpw_h + (size_t)layer * 2 * 64 * DI,
            xpw_l + (size_t)layer * 2 * 64 * DI, DI, (long)64 * DI,
            dbcv, DBCN, (long)MROWS * DBCN, DBCN,
            DI/64, nullptr, 0, nullptr, dbch, dbcl);

        // dt = softplus(dbc[:, :24] @ dt_w + dt_b)  (S=1 -> single-stage smem, 3 CTAs/SM)
        mma_gemm<128,1,true,true,false><<<dim3(6, MT, 2), 256, SM_A2B2_128_S1>>>(
            dbch, dbcl, DBCN, (long)MROWS * DBCN,
            dtw_h + (size_t)layer * 2 * DI * 64,
            dtw_l + (size_t)layer * 2 * DI * 64, 64, (long)DI * 64,
            dtv, DI, (long)MROWS * DI, DI,
            1, dt_b + (size_t)layer * 2 * DI, (long)DI, nullptr, nullptr, nullptr);

        scan_kernel<<<dim3(6, BATCHN, 2), 128>>>(
            dtv, u_h, u_l, dbcv, xz,
            A_log + (size_t)layer * 2 * DI * DS, Dp + (size_t)layer * 2 * DI,
            y_h);

        // x += y @ out_w  (single-plane, dirs stacked K=1536)
        mma_gemm<128,2,false,false,false><<<dim3(3, MT, 1), 256, SM_A1B1_128>>>(
            y_h, nullptr, 2*DI, 0,
            outw_h + (size_t)layer * DM * 2*DI, nullptr, 2*DI, 0,
            x, DM, 0, DM,
            2*DI/64, nullptr, 0, x, nullptr, nullptr);
    }

    // final LN (fp32, into xz scratch) + pool + heads
    ln_f32<<<MROWS, 128>>>(x, xz, fln_g, fln_b);
    pool_head<<<BATCHN, 384>>>(xz, hdev_w, hdev_b, hdist_w, hdist_b, out);
    (void)in_sizes; (void)n_in; (void)out_size;
}

// round 17
// speedup vs baseline: 1.0662x; 1.0037x over previous
#include <cuda_runtime.h>
#include <cuda_fp16.h>
#include <math.h>
#include <stdint.h>

#define BATCHN 32
#define LSEQ   196
#define DM     384
#define DI     768
#define DS     16
#define DTR    24
#define DBCN   56
#define DEPTH  12
#define MROWS  (BATCHN*LSEQ)   // 6272

#if defined(__CUDA_ARCH__) && (defined(__CUDA_ARCH_FEAT_SM103_ALL) || defined(__CUDA_ARCH_SPECIFIC__))
#define HAS_TC 1
#else
#define HAS_TC 0
#endif

typedef __half f16;

// ---------------- scratch ----------------
__device__ __align__(256) float g_x  [MROWS*DM];
__device__ __align__(256) float g_xz [2*MROWS*2*DI];      // also reused as final-LN scratch
__device__ __align__(256) float g_dbc[2*MROWS*DBCN];
__device__ __align__(256) float g_dt [2*MROWS*DI];

__device__ __align__(256) f16 g_xn_h[MROWS*DM];
__device__ __align__(256) f16 g_im_h[MROWS*768];
__device__ __align__(256) f16 g_u_h [2*MROWS*DI],  g_u_l [2*MROWS*DI];
__device__ __align__(256) f16 g_y_h [MROWS*2*DI];
__device__ __align__(256) f16 g_dbch[2*MROWS*DBCN + 128], g_dbcl[2*MROWS*DBCN + 128];
__device__ __align__(256) f16 g_inw_h [DEPTH*2*2*DI*DM];
__device__ __align__(256) f16 g_outw_h[DEPTH*DM*2*DI];
__device__ __align__(256) f16 g_xpw_h [DEPTH*2*64*DI],   g_xpw_l [DEPTH*2*64*DI];
__device__ __align__(256) f16 g_dtw_h [DEPTH*2*DI*64],   g_dtw_l [DEPTH*2*DI*64]; // cols>=24 zero
__device__ __align__(256) f16 g_pw_h  [DM*768];

__device__ __forceinline__ void split2(float v, f16& h, f16& l) {
    h = __float2half_rn(v);
    l = __float2half_rn(v - __half2float(h));
}

#if HAS_TC
__device__ __forceinline__ uint32_t smem_u32(const void* p) {
    uint32_t a;
    asm("{ .reg .u64 t; cvta.to.shared.u64 t, %1; cvt.u32.u64 %0, t; }" : "=r"(a) : "l"(p));
    return a;
}
__device__ __forceinline__ uint32_t elect_one() {
    uint32_t p;
    asm volatile("{ .reg .pred p; elect.sync _|p, 0xFFFFFFFF; selp.b32 %0,1,0,p; }" : "=r"(p));
    return p;
}
#define SWZ(o) ((o) ^ (((o) >> 3) & 0x70))

static __device__ __forceinline__ uint64_t make_desc(uint32_t addr) {
    const uint64_t base =
        (uint64_t(2) << 61) | (uint64_t(1) << 46) | (uint64_t(64) << 32) | (uint64_t(1) << 16);
    return base | ((uint64_t)(addr >> 4) & 0x3FFF);
}

#define MBAR_INIT(a, c) \
    asm volatile("mbarrier.init.shared.b64 [%0], %1;" :: "r"(a), "r"(c) : "memory")
#define MBAR_INVAL(a) \
    asm volatile("mbarrier.inval.shared.b64 [%0];" :: "r"(a) : "memory")
#define MBAR_WAIT(a, ph) do {                                            \
    uint32_t _m = (a); uint32_t _p = (ph); uint32_t _d;                  \
    asm volatile("{ .reg .pred p; mbarrier.try_wait.parity.acquire.cta.shared::cta.b64 p,[%1],%2; selp.b32 %0,1,0,p; }" \
        : "=r"(_d) : "r"(_m), "r"(_p) : "memory");                       \
    if (!_d) {                                                           \
        asm volatile("{ .reg .pred P1; W%=: mbarrier.try_wait.parity.acquire.cta.shared::cta.b64 P1,[%0],%1,0x989680; @P1 bra.uni D%=; bra.uni W%=; D%=: }" \
            :: "r"(_m), "r"(_p) : "memory");                             \
    } } while (0)

#define CP_ASYNC16(dst, src) \
    asm volatile("cp.async.cg.shared.global [%0], [%1], 16;" :: "r"(dst), "l"(src) : "memory")
#define CP_COMMIT() asm volatile("cp.async.commit_group;" ::: "memory")
// One commit per iteration; step s's data is in group s+1 (2-stage) or
// <= s+2 (3-stage) of the (STAGES+s) committed before iter s -> wait 1 ok.
#define CP_WAIT1()  asm volatile("cp.async.wait_group 1;" ::: "memory")

__device__ __forceinline__ void tc_alloc(uint32_t smem_dst, uint32_t ncols) {
    asm volatile("tcgen05.alloc.cta_group::1.sync.aligned.shared::cta.b32 [%0], %1;"
                 :: "r"(smem_dst), "r"(ncols) : "memory");
}
__device__ __forceinline__ void tc_relinq() {
    asm volatile("tcgen05.relinquish_alloc_permit.cta_group::1.sync.aligned;");
}
__device__ __forceinline__ void tc_dealloc(uint32_t tmem, uint32_t ncols) {
    asm volatile("tcgen05.dealloc.cta_group::1.sync.aligned.b32 %0, %1;" :: "r"(tmem), "r"(ncols));
}
__device__ __forceinline__ void tc_commit(uint32_t mbar) {
    asm volatile("tcgen05.commit.cta_group::1.mbarrier::arrive::one.shared::cluster.b64 [%0];"
                 :: "r"(mbar) : "memory");
}
__device__ __forceinline__ void mma_f16(uint32_t d, uint64_t ad, uint64_t bd, uint32_t idesc, bool acc) {
    uint32_t en = acc ? 1u : 0u, z = 0u;
    asm volatile(
        "{ .reg .pred p; setp.ne.u32 p, %5, 0;"
        " tcgen05.mma.cta_group::1.kind::f16 [%0], %1, %2, %3, {%4,%4,%4,%4}, p; }"
        :: "r"(d), "l"(ad), "l"(bd), "r"(idesc), "r"(z), "r"(en) : "memory");
}
#define TC_LD_X32(r, a)                                                     \
    asm volatile("tcgen05.ld.sync.aligned.32x32b.x32.b32 "                  \
        "{%0,%1,%2,%3,%4,%5,%6,%7,%8,%9,%10,%11,%12,%13,%14,%15,"           \
        "%16,%17,%18,%19,%20,%21,%22,%23,%24,%25,%26,%27,%28,%29,%30,%31}, [%32];" \
        : "=r"((r)[0]),"=r"((r)[1]),"=r"((r)[2]),"=r"((r)[3]),"=r"((r)[4]),"=r"((r)[5]),"=r"((r)[6]),"=r"((r)[7]), \
          "=r"((r)[8]),"=r"((r)[9]),"=r"((r)[10]),"=r"((r)[11]),"=r"((r)[12]),"=r"((r)[13]),"=r"((r)[14]),"=r"((r)[15]), \
          "=r"((r)[16]),"=r"((r)[17]),"=r"((r)[18]),"=r"((r)[19]),"=r"((r)[20]),"=r"((r)[21]),"=r"((r)[22]),"=r"((r)[23]), \
          "=r"((r)[24]),"=r"((r)[25]),"=r"((r)[26]),"=r"((r)[27]),"=r"((r)[28]),"=r"((r)[29]),"=r"((r)[30]),"=r"((r)[31]) \
        : "r"(a))
#define TC_WAIT_LD() asm volatile("tcgen05.wait::ld.sync.aligned;" ::: "memory")
#define TC_FENCE_AFTER() asm volatile("tcgen05.fence::after_thread_sync;" ::: "memory")

// ---- packed f32x2 helpers (sm_103a) ----
__device__ __forceinline__ uint64_t pk2(float lo, float hi) {
    uint64_t r; asm("mov.b64 %0, {%1, %2};" : "=l"(r) : "f"(lo), "f"(hi)); return r;
}
__device__ __forceinline__ void upk2(uint64_t v, float& lo, float& hi) {
    asm("mov.b64 {%0, %1}, %2;" : "=f"(lo), "=f"(hi) : "l"(v));
}
__device__ __forceinline__ uint64_t mul2(uint64_t a, uint64_t b) {
    uint64_t r; asm("mul.rn.f32x2 %0, %1, %2;" : "=l"(r) : "l"(a), "l"(b)); return r;
}
__device__ __forceinline__ uint64_t fma2(uint64_t a, uint64_t b, uint64_t c) {
    uint64_t r; asm("fma.rn.f32x2 %0, %1, %2, %3;" : "=l"(r) : "l"(a), "l"(b), "l"(c)); return r;
}
#endif  // HAS_TC

__device__ __forceinline__ float softplusf(float v) {
    return (v > 0.f) ? v + log1pf(__expf(-v)) : log1pf(__expf(v));
}

// =====================================================================
// fp16 tcgen05 GEMM, STAGES-deep cp.async ring, 256 threads.
// C = (Ah[+Al]) @ ((Bh[+Bl])^T  in fp32 accum.
// MMA groups: AhBh [+ AlBh if ASPLIT] [+ AhBl if BSPLIT].
// K-step = 64 elements. S = K/64. Only min(S,STAGES) stages touched.
// EPI: 0 plain, 1 softplus(v+bias), 2 v+res, 3 v+bias+res[(m%L)*ldc+col]
// =====================================================================
template<int NT, int STAGES, int EPI, bool ASPLIT, bool BSPLIT, bool SPLITOUT>
__global__ void __launch_bounds__(256) mma_gemm(
    const f16* __restrict__ Ah, const f16* __restrict__ Al, int lda, long sA,
    const f16* __restrict__ Bh, const f16* __restrict__ Bl, int ldb, long sB,
    float* __restrict__ C, int ldc, long sC, int Ncols,
    int S,
    const float* __restrict__ bias, long sBias,
    const float* __restrict__ res,
    f16* __restrict__ Ch, f16* __restrict__ Cl)
{
    const int tid = threadIdx.x;
    const int m0 = blockIdx.y * 128, n0 = blockIdx.x * NT;
    Ah += (size_t)blockIdx.z * sA;
    if (ASPLIT) Al += (size_t)blockIdx.z * sA;
    Bh += (size_t)blockIdx.z * sB;
    if (BSPLIT) Bl += (size_t)blockIdx.z * sB;
    C  += (size_t)blockIdx.z * sC;
    if (bias) bias += (size_t)blockIdx.z * sBias;
    if (SPLITOUT) { Ch += (size_t)blockIdx.z * sC; Cl += (size_t)blockIdx.z * sC; }

#if HAS_TC
    extern __shared__ char smem[];
    const uint32_t sb = smem_u32(smem);
    const int wid = tid >> 5, lane = tid & 31;
    constexpr int ABYTES = 128 * 128;
    constexpr int BBYTES = NT * 128;
    constexpr int NA     = ASPLIT ? 2 : 1;
    constexpr int NB     = BSPLIT ? 2 : 1;
    constexpr int STAGE  = NA * ABYTES + NB * BBYTES;

    if (tid == 0) {
#pragma unroll
        for (int i = 0; i < STAGES; i++) MBAR_INIT(sb + 8 + i * 8, 1);
    }
    if (wid == 0) { tc_alloc(sb, NT); tc_relinq(); }
    __syncthreads();
    uint32_t tmem;
    asm volatile("ld.shared.b32 %0, [%1];" : "=r"(tmem) : "r"(sb));

    const uint32_t idesc = 0x10u | ((uint32_t)(NT / 8) << 17) | (8u << 24);

    auto stage_load = [&](int r, int step) {
        const int k0 = step << 6;
        const uint32_t ah = sb + 1024 + r * STAGE;
        const uint32_t al = ah + ABYTES;
        const uint32_t bh = ah + NA * ABYTES;
        const uint32_t bl = bh + BBYTES;
#pragma unroll
        for (int i = 0; i < 4; i++) {
            int c = i * 256 + tid; int row = c >> 3, q = c & 7;
            uint32_t so = SWZ(row * 128 + q * 16);
            size_t go = (size_t)(m0 + row) * lda + k0 + q * 8;
            CP_ASYNC16(ah + so, Ah + go);
            if (ASPLIT) CP_ASYNC16(al + so, Al + go);
        }
#pragma unroll
        for (int i = 0; i < NT / 32; i++) {
            int c = i * 256 + tid; int row = c >> 3, q = c & 7;
            uint32_t so = SWZ(row * 128 + q * 16);
            size_t go = (size_t)(n0 + row) * ldb + k0 + q * 8;
            CP_ASYNC16(bh + so, Bh + go);
            if (BSPLIT) CP_ASYNC16(bl + so, Bl + go);
        }
    };

#pragma unroll
    for (int p = 0; p < STAGES; p++) { if (p < S) stage_load(p, p); CP_COMMIT(); }

    int ph[STAGES];
#pragma unroll
    for (int i = 0; i < STAGES; i++) ph[i] = 0;

    for (int s = 0; s < S; s++) {
        CP_WAIT1();
        asm volatile("fence.proxy.async.shared::cta;" ::: "memory");
        __syncthreads();
        const int st = s % STAGES;
        if (wid == 0 && elect_one()) {
            const uint32_t ah = sb + 1024 + st * STAGE;
            uint64_t adh = make_desc(ah);
            uint64_t bdh = make_desc(ah + NA * ABYTES);
#pragma unroll
            for (int sl = 0; sl < 4; sl++)
                mma_f16(tmem, adh + sl * 2, bdh + sl * 2, idesc, (s > 0) || (sl > 0));
            if (ASPLIT) {
                uint64_t adl = make_desc(ah + ABYTES);
#pragma unroll
                for (int sl = 0; sl < 4; sl++)
                    mma_f16(tmem, adl + sl * 2, bdh + sl * 2, idesc, true);
            }
            if (BSPLIT) {
                uint64_t bdl = make_desc(ah + NA * ABYTES + BBYTES);
#pragma unroll
                for (int sl = 0; sl < 4; sl++)
                    mma_f16(tmem, adh + sl * 2, bdl + sl * 2, idesc, true);
            }
            tc_commit(sb + 8 + st * 8);
        }
        if (STAGES == 3) {
            // refill stage holding step s-1 with step s+2 (gated on MMA(s-1))
            if (s >= 1 && s + 2 < S) {
                const int r = (s + 2) % 3;
                MBAR_WAIT(sb + 8 + r * 8, ph[r]); ph[r] ^= 1;
                stage_load(r, s + 2);
            }
        } else {
            // 2-stage: refill current stage with step s+2 (gated on MMA(s))
            if (s + 2 < S) {
                MBAR_WAIT(sb + 8 + st * 8, ph[st]); ph[st] ^= 1;
                stage_load(st, s + 2);
            }
        }
        CP_COMMIT();
    }
    MBAR_WAIT(sb + 8 + ((S - 1) % STAGES) * 8, ph[(S - 1) % STAGES]);
    TC_FENCE_AFTER();

    const int subp = wid & 3, half = wid >> 2;
#pragma unroll
    for (int ch = 0; ch < NT / 64; ch++) {
        const int chunk = half * (NT / 64) + ch;
        uint32_t r[32];
        TC_LD_X32(r, tmem + chunk * 32);
        TC_WAIT_LD();
        const int row = m0 + subp * 32 + lane;
        const int col0 = n0 + chunk * 32;
        float* cp = C + (size_t)row * ldc + col0;
        float vals[32];
#pragma unroll
        for (int j = 0; j < 32; j++) {
            float v = __uint_as_float(r[j]);
            const int col = col0 + j;
            if (EPI == 1) v = softplusf(v + bias[col]);
            if (EPI == 2) v += res[(size_t)row * ldc + col];
            if (EPI == 3) v += bias[col] + res[(size_t)(row % LSEQ) * ldc + col];
            vals[j] = v;
        }
        if (col0 + 31 < Ncols) {
#pragma unroll
            for (int g = 0; g < 8; g++)
                *(float4*)(cp + g * 4) =
                    make_float4(vals[4*g], vals[4*g+1], vals[4*g+2], vals[4*g+3]);
            if (SPLITOUT) {
#pragma unroll
                for (int j = 0; j < 32; j++) {
                    f16 hh, ll; split2(vals[j], hh, ll);
                    Ch[(size_t)row * ldc + col0 + j] = hh;
                    Cl[(size_t)row * ldc + col0 + j] = ll;
                }
            }
        } else {
#pragma unroll
            for (int j = 0; j < 32; j++)
                if (col0 + j < Ncols) {
                    cp[j] = vals[j];
                    if (SPLITOUT) {
                        f16 hh, ll; split2(vals[j], hh, ll);
                        Ch[(size_t)row * ldc + col0 + j] = hh;
                        Cl[(size_t)row * ldc + col0 + j] = ll;
                    }
                }
        }
    }
    __syncthreads();
    if (tid == 0) {
#pragma unroll
        for (int i = 0; i < STAGES; i++) MBAR_INVAL(sb + 8 + i * 8);
    }
    if (wid == 0) tc_dealloc(tmem, NT);
#else
    if (tid >= 128) return;
    const int row = m0 + tid;
    const int K = S * 64;
    for (int n = 0; n < NT; n++) {
        const int col = n0 + n;
        if (col >= Ncols) break;
        float acc = 0.f;
        for (int k = 0; k < K; k++) {
            float a = __half2float(Ah[(size_t)row * lda + k]);
            if (ASPLIT) a += __half2float(Al[(size_t)row * lda + k]);
            float b = __half2float(Bh[(size_t)col * ldb + k]);
            if (BSPLIT) b += __half2float(Bl[(size_t)col * ldb + k]);
            acc = fmaf(a, b, acc);
        }
        float v = acc;
        if (EPI == 1) v = softplusf(v + bias[col]);
        if (EPI == 2) v += res[(size_t)row * ldc + col];
        if (EPI == 3) v += bias[col] + res[(size_t)(row % LSEQ) * ldc + col];
        C[(size_t)row * ldc + col] = v;
        if (SPLITOUT) {
            f16 hh, ll; split2(v, hh, ll);
            Ch[(size_t)row * ldc + col] = hh;
            Cl[(size_t)row * ldc + col] = ll;
        }
    }
#endif
}

// ---- transpose + zero-pad + fp16-split (two planes) ----
__global__ void __launch_bounds__(256) transpose_split(
    const float* __restrict__ in, f16* __restrict__ oh, f16* __restrict__ ol,
    int R, int C, int OR_, int OC)
{
    __shared__ float t[32][33];
    const int z = blockIdx.z;
    in += (size_t)z * R * C;
    oh += (size_t)z * OR_ * OC;
    ol += (size_t)z * OR_ * OC;
    const int j0 = blockIdx.x * 32;
    const int i0 = blockIdx.y * 32;
    const int tx = threadIdx.x & 31, ty = threadIdx.x >> 5;
#pragma unroll
    for (int k = 0; k < 4; k++) {
        int rin = j0 + ty + k * 8, cin = i0 + tx;
        t[ty + k * 8][tx] = (rin < R && cin < C) ? in[(size_t)rin * C + cin] : 0.f;
    }
    __syncthreads();
#pragma unroll
    for (int k = 0; k < 4; k++) {
        int orow = i0 + ty + k * 8, ocol = j0 + tx;
        if (orow < OR_ && ocol < OC) {
            f16 h, l; split2(t[tx][ty + k * 8], h, l);
            oh[(size_t)orow * OC + ocol] = h;
            ol[(size_t)orow * OC + ocol] = l;
        }
    }
}

// ---- transpose + fp16 single plane ----
__global__ void __launch_bounds__(256) transpose_h(
    const float* __restrict__ in, f16* __restrict__ oh, int R, int C)
{
    __shared__ float t[32][33];
    const int z = blockIdx.z;
    in += (size_t)z * R * C;
    oh += (size_t)z * R * C;
    const int j0 = blockIdx.x * 32;
    const int i0 = blockIdx.y * 32;
    const int tx = threadIdx.x & 31, ty = threadIdx.x >> 5;
#pragma unroll
    for (int k = 0; k < 4; k++)
        t[ty + k * 8][tx] = in[(size_t)(j0 + ty + k * 8) * C + i0 + tx];
    __syncthreads();
#pragma unroll
    for (int k = 0; k < 4; k++)
        oh[(size_t)(i0 + ty + k * 8) * R + j0 + tx] = __float2half_rn(t[tx][ty + k * 8]);
}

__global__ void half_copy(const float* __restrict__ in, f16* __restrict__ oh, int n)
{
    int i = blockIdx.x * blockDim.x + threadIdx.x;
    if (i < n) oh[i] = __float2half_rn(in[i]);
}

// ---------------- LayerNorm -> fp16 single ----------------
__global__ void __launch_bounds__(128) ln_kernel(
    const float* __restrict__ x, f16* __restrict__ yh,
    const float* __restrict__ g, const float* __restrict__ b)
{
    const int row = blockIdx.x;
    const int tid = threadIdx.x;
    const float* xr = x + (size_t)row * DM;
    float v0 = xr[tid], v1 = xr[tid + 128], v2 = xr[tid + 256];
    __shared__ float sh[4];
    float s = v0 + v1 + v2;
#pragma unroll
    for (int o = 16; o > 0; o >>= 1) s += __shfl_xor_sync(0xffffffffu, s, o);
    if ((tid & 31) == 0) sh[tid >> 5] = s;
    __syncthreads();
    float mu = (sh[0] + sh[1] + sh[2] + sh[3]) * (1.f / DM);
    float d0 = v0 - mu, d1 = v1 - mu, d2 = v2 - mu;
    float q = d0*d0 + d1*d1 + d2*d2;
    __syncthreads();
#pragma unroll
    for (int o = 16; o > 0; o >>= 1) q += __shfl_xor_sync(0xffffffffu, q, o);
    if ((tid & 31) == 0) sh[tid >> 5] = q;
    __syncthreads();
    float var = (sh[0] + sh[1] + sh[2] + sh[3]) * (1.f / DM);
    float rs = rsqrtf(var + 1e-5f);
    size_t base = (size_t)row * DM;
    yh[base + tid]       = __float2half_rn(d0 * rs * g[tid]       + b[tid]);
    yh[base + tid + 128] = __float2half_rn(d1 * rs * g[tid + 128] + b[tid + 128]);
    yh[base + tid + 256] = __float2half_rn(d2 * rs * g[tid + 256] + b[tid + 256]);
}

// ---------------- final LayerNorm -> fp32 ----------------
__global__ void __launch_bounds__(128) ln_f32(
    const float* __restrict__ x, float* __restrict__ y,
    const float* __restrict__ g, const float* __restrict__ b)
{
    const int row = blockIdx.x;
    const int tid = threadIdx.x;
    const float* xr = x + (size_t)row * DM;
    float v0 = xr[tid], v1 = xr[tid + 128], v2 = xr[tid + 256];
    __shared__ float sh[4];
    float s = v0 + v1 + v2;
#pragma unroll
    for (int o = 16; o > 0; o >>= 1) s += __shfl_xor_sync(0xffffffffu, s, o);
    if ((tid & 31) == 0) sh[tid >> 5] = s;
    __syncthreads();
    float mu = (sh[0] + sh[1] + sh[2] + sh[3]) * (1.f / DM);
    float d0 = v0 - mu, d1 = v1 - mu, d2 = v2 - mu;
    float q = d0*d0 + d1*d1 + d2*d2;
    __syncthreads();
#pragma unroll
    for (int o = 16; o > 0; o >>= 1) q += __shfl_xor_sync(0xffffffffu, q, o);
    if ((tid & 31) == 0) sh[tid >> 5] = q;
    __syncthreads();
    float var = (sh[0] + sh[1] + sh[2] + sh[3]) * (1.f / DM);
    float rs = rsqrtf(var + 1e-5f);
    float* yr = y + (size_t)row * DM;
    yr[tid]       = d0 * rs * g[tid]       + b[tid];
    yr[tid + 128] = d1 * rs * g[tid + 128] + b[tid + 128];
    yr[tid + 256] = d2 * rs * g[tid + 256] + b[tid + 256];
}

// ---------------- conv1d + SiLU, 4 channels/thread (R11-proven) ----------------
__global__ void conv_silu(const float* __restrict__ xz, const float* __restrict__ w,
                          const float* __restrict__ bias,
                          f16* __restrict__ uh, f16* __restrict__ ul)
{
    const int CQ = DI / 4;
    int idx = blockIdx.x * blockDim.x + threadIdx.x;
    if (idx >= 2 * MROWS * CQ) return;
    int q   = idx % CQ;  int c4 = q * 4;
    int m   = (idx / CQ) % MROWS;
    int dir = idx / (CQ * MROWS);
    int l = m % LSEQ, mbase = m - l;
    const float* xzd = xz + (size_t)dir * MROWS * 2 * DI;
    const float* wp = w + (size_t)dir * DI * 4 + c4 * 4;
    float4 w0 = *(const float4*)(wp);
    float4 w1 = *(const float4*)(wp + 4);
    float4 w2 = *(const float4*)(wp + 8);
    float4 w3 = *(const float4*)(wp + 12);
    float4 bv = *(const float4*)(bias + dir * DI + c4);
    float a0 = bv.x, a1 = bv.y, a2 = bv.z, a3 = bv.w;
    const float wk0[4] = {w0.x, w0.y, w0.z, w0.w};
    const float wk1[4] = {w1.x, w1.y, w1.z, w1.w};
    const float wk2[4] = {w2.x, w2.y, w2.z, w2.w};
    const float wk3[4] = {w3.x, w3.y, w3.z, w3.w};
#pragma unroll
    for (int k = 0; k < 4; k++) {
        int ls = dir ? (l + 3 - k) : (l - 3 + k);
        if (ls >= 0 && ls < LSEQ) {
            float4 xv = *(const float4*)(xzd + (size_t)(mbase + ls) * 2 * DI + c4);
            a0 = fmaf(wk0[k], xv.x, a0);
            a1 = fmaf(wk1[k], xv.y, a1);
            a2 = fmaf(wk2[k], xv.z, a2);
            a3 = fmaf(wk3[k], xv.w, a3);
        }
    }
    float u0 = a0 / (1.f + __expf(-a0));
    float u1 = a1 / (1.f + __expf(-a1));
    float u2 = a2 / (1.f + __expf(-a2));
    float u3 = a3 / (1.f + __expf(-a3));
    size_t o = (size_t)dir * MROWS * DI + (size_t)m * DI + c4;
    f16 h0,l0,h1,l1,h2,l2,h3,l3;
    split2(u0,h0,l0); split2(u1,h1,l1); split2(u2,h2,l2); split2(u3,h3,l3);
    __half2* uhp = (__half2*)(uh + o);
    __half2* ulp = (__half2*)(ul + o);
    uhp[0] = __halves2half2(h0, h1);
    uhp[1] = __halves2half2(h2, h3);
    ulp[0] = __halves2half2(l0, l1);
    ulp[1] = __halves2half2(l2, l3);
}

// ---------------- selective scan (packed f32x2 fast path) -> y fp16 ----------------
__global__ void __launch_bounds__(128) scan_kernel(
    const float* __restrict__ dt,
    const f16* __restrict__ uh, const f16* __restrict__ ul,
    const float* __restrict__ dbc, const float* __restrict__ xz,
    const float* __restrict__ A_log, const float* __restrict__ Dp,
    f16* __restrict__ yh)
{
    const int c   = blockIdx.x * 128 + threadIdx.x;
    const int b   = blockIdx.y;
    const int dir = blockIdx.z;

    __shared__ __align__(16) float Bsh[LSEQ][DS];
    __shared__ __align__(16) float Csh[LSEQ][DS];
    const float* dbcb = dbc + ((size_t)dir * MROWS + (size_t)b * LSEQ) * DBCN;
    for (int i = threadIdx.x; i < LSEQ * 2 * DS; i += 128) {
        int l = i >> 5, j = i & 31;
        float v = dbcb[(size_t)l * DBCN + DTR + j];
        if (j < DS) Bsh[l][j] = v; else Csh[l][j - DS] = v;
    }
    __syncthreads();

    float a[DS];
    const float* ap = A_log + ((size_t)dir * DI + c) * DS;
#pragma unroll
    for (int n = 0; n < DS; n++) a[n] = -__expf(ap[n]);
    const float a0 = a[0];
    bool fast = true;
#pragma unroll
    for (int n = 1; n < DS; n++)
        fast = fast && (fabsf(a[n] - a0 * (float)(n + 1)) <= 1e-4f * fabsf(a[n]));
    const float dp = Dp[dir * DI + c];

    const size_t ubase = ((size_t)dir * MROWS + (size_t)b * LSEQ) * DI + c;
    const float* dtb = dt + ubase;
    const float* zb  = xz + ((size_t)dir * MROWS + (size_t)b * LSEQ) * 2 * DI + DI + c;
    const size_t ybase = ((size_t)b * LSEQ) * 2 * DI + (size_t)dir * DI + c;

    int l = dir ? (LSEQ - 1) : 0;
    float dt_n = dtb[(size_t)l * DI];
    float uh_n = __half2float(uh[ubase + (size_t)l * DI]);
    float ul_n = __half2float(ul[ubase + (size_t)l * DI]);
    float z_n  = zb[(size_t)l * 2 * DI];

#if HAS_TC
    if (fast) {
        uint64_t h2[8];
#pragma unroll
        for (int k = 0; k < 8; k++) h2[k] = 0ull;
        for (int t = 0; t < LSEQ; t++) {
            const int lc = l;
            const float dtv = dt_n;
            const float uv  = uh_n + ul_n;
            const float zv  = z_n;
            if (t + 1 < LSEQ) {
                l = dir ? (LSEQ - 2 - t) : (t + 1);
                dt_n = dtb[(size_t)l * DI];
                uh_n = __half2float(uh[ubase + (size_t)l * DI]);
                ul_n = __half2float(ul[ubase + (size_t)l * DI]);
                z_n  = zb[(size_t)l * 2 * DI];
            }
            const float du = dtv * uv;
            const float e1 = __expf(dtv * a0);
            const float e2 = e1 * e1;
            const uint64_t E2  = pk2(e2, e2);
            const uint64_t du2 = pk2(du, du);
            uint64_t p = pk2(e1, e2);
            uint64_t acc2 = pk2(0.f, 0.f);
            const uint64_t* B2 = (const uint64_t*)&Bsh[lc][0];
            const uint64_t* C2 = (const uint64_t*)&Csh[lc][0];
#pragma unroll
            for (int k = 0; k < 8; k++) {
                if (k > 0) p = mul2(p, E2);
                uint64_t tmp = mul2(du2, B2[k]);
                h2[k] = fma2(p, h2[k], tmp);
                acc2 = fma2(h2[k], C2[k], acc2);
            }
            float alo, ahi; upk2(acc2, alo, ahi);
            const float yv = alo + ahi + dp * uv;
            const float og = yv * (zv / (1.f + __expf(-zv)));
            yh[ybase + (size_t)lc * 2 * DI] = __float2half_rn(og);
        }
        return;
    }
#endif
    float h[DS];
#pragma unroll
    for (int n = 0; n < DS; n++) h[n] = 0.f;
    for (int t = 0; t < LSEQ; t++) {
        const int lc = l;
        const float dtv = dt_n;
        const float uv  = uh_n + ul_n;
        const float zv  = z_n;
        if (t + 1 < LSEQ) {
            l = dir ? (LSEQ - 2 - t) : (t + 1);
            dt_n = dtb[(size_t)l * DI];
            uh_n = __half2float(uh[ubase + (size_t)l * DI]);
            ul_n = __half2float(ul[ubase + (size_t)l * DI]);
            z_n  = zb[(size_t)l * 2 * DI];
        }
        const float du = dtv * uv;
        float acc = 0.f;
        if (fast) {
            const float e1 = __expf(dtv * a0);
            float p = 1.f;
#pragma unroll
            for (int n = 0; n < DS; n++) {
                p *= e1;
                h[n] = p * h[n] + du * Bsh[lc][n];
                acc = fmaf(h[n], Csh[lc][n], acc);
            }
        } else {
#pragma unroll
            for (int n = 0; n < DS; n++) {
                h[n] = __expf(dtv * a[n]) * h[n] + du * Bsh[lc][n];
                acc = fmaf(h[n], Csh[lc][n], acc);
            }
        }
        const float yv = acc + dp * uv;
        const float og = yv * (zv / (1.f + __expf(-zv)));
        yh[ybase + (size_t)lc * 2 * DI] = __float2half_rn(og);
    }
}

// ---------------- pool + heads (after ln_f32) ----------------
__global__ void __launch_bounds__(384) pool_head(
    const float* __restrict__ fln,
    const float* __restrict__ wdev, const float* __restrict__ bdev,
    const float* __restrict__ wdist, const float* __restrict__ bdist,
    float* __restrict__ out)
{
    const int b = blockIdx.x;
    const int tid = threadIdx.x;
    __shared__ float pooled_s[DM];
    float s = 0.f;
    for (int l = 0; l < LSEQ; l++)
        s += fln[((size_t)b * LSEQ + l) * DM + tid];
    pooled_s[tid] = s * (1.f / LSEQ);
    __syncthreads();
    if (tid < 7) {
        float acc = bdev[tid];
        for (int d = 0; d < DM; d++) acc += pooled_s[d] * wdev[d * 7 + tid];
        out[b * 7 + tid] = acc;
    } else if (tid < 11) {
        int j = tid - 7;
        float acc = bdist[j];
        for (int d = 0; d < DM; d++) acc += pooled_s[d] * wdist[d * 4 + j];
        out[BATCHN * 7 + b * 4 + j] = acc;
    }
}

// ---------------- im2col -> fp16 single ----------------
__global__ void im2col_kernel(const float* __restrict__ img)
{
    int idx = blockIdx.x * blockDim.x + threadIdx.x;
    if (idx >= MROWS * 768) return;
    int k = idx % 768;
    int m = idx / 768;
    int b = m / LSEQ, l = m % LSEQ;
    int ph = l / 14, pw = l % 14;
    int ch  = k >> 8;
    int r   = (k >> 4) & 15;
    int col = k & 15;
    float v = img[(((size_t)b * 3 + ch) * 224 + ph * 16 + r) * 224 + pw * 16 + col];
    g_im_h[idx] = __float2half_rn(v);
}

// ---------------- launcher ----------------
extern "C" void kernel_launch(void* const* d_in, const int* in_sizes, int n_in,
                              void* d_out, int out_size)
{
    const float* images  = (const float*)d_in[0];
    const float* patch_w = (const float*)d_in[1];
    const float* patch_b = (const float*)d_in[2];
    const float* pos_emb = (const float*)d_in[3];
    const float* ln_g    = (const float*)d_in[4];
    const float* ln_b    = (const float*)d_in[5];
    const float* in_w    = (const float*)d_in[6];
    const float* conv_w  = (const float*)d_in[7];
    const float* conv_b  = (const float*)d_in[8];
    const float* xproj_w = (const float*)d_in[9];
    const float* dt_w    = (const float*)d_in[10];
    const float* dt_b    = (const float*)d_in[11];
    const float* A_log   = (const float*)d_in[12];
    const float* Dp      = (const float*)d_in[13];
    const float* out_w   = (const float*)d_in[14];
    const float* fln_g   = (const float*)d_in[15];
    const float* fln_b   = (const float*)d_in[16];
    const float* hdev_w  = (const float*)d_in[17];
    const float* hdev_b  = (const float*)d_in[18];
    const float* hdist_w = (const float*)d_in[19];
    const float* hdist_b = (const float*)d_in[20];
    float* out = (float*)d_out;

    float *x, *xz, *dbcv, *dtv;
    f16 *xn_h, *im_h, *u_h, *u_l, *y_h, *dbch, *dbcl;
    f16 *inw_h, *outw_h, *xpw_h, *xpw_l, *dtw_h, *dtw_l, *pw_h;
    cudaGetSymbolAddress((void**)&x,     g_x);
    cudaGetSymbolAddress((void**)&xz,    g_xz);
    cudaGetSymbolAddress((void**)&dbcv,  g_dbc);
    cudaGetSymbolAddress((void**)&dtv,   g_dt);
    cudaGetSymbolAddress((void**)&xn_h,  g_xn_h);
    cudaGetSymbolAddress((void**)&im_h,  g_im_h);
    cudaGetSymbolAddress((void**)&u_h,   g_u_h);   cudaGetSymbolAddress((void**)&u_l,   g_u_l);
    cudaGetSymbolAddress((void**)&y_h,   g_y_h);
    cudaGetSymbolAddress((void**)&dbch,  g_dbch);  cudaGetSymbolAddress((void**)&dbcl,  g_dbcl);
    cudaGetSymbolAddress((void**)&inw_h, g_inw_h);
    cudaGetSymbolAddress((void**)&outw_h,g_outw_h);
    cudaGetSymbolAddress((void**)&xpw_h, g_xpw_h); cudaGetSymbolAddress((void**)&xpw_l, g_xpw_l);
    cudaGetSymbolAddress((void**)&dtw_h, g_dtw_h); cudaGetSymbolAddress((void**)&dtw_l, g_dtw_l);
    cudaGetSymbolAddress((void**)&pw_h,  g_pw_h);

    // smem: 1024 + nStages * STAGE (only min(S,STAGES) stages are touched)
    const int SM_IN_2ST   = 1024 + 2 * (16384 + 16384);             // 66560  (3 CTAs/SM)
    const int SM_A1B1_128 = 1024 + 3 * (16384 + 16384);             // 99328  (2 CTAs/SM)
    const int SM_A2B2_64  = 1024 + 3 * (2 * 16384 + 2 * 64 * 128);  // 148480
    const int SM_A2B2_128_S1 = 1024 + 1 * (2 * 16384 + 2 * 128 * 128); // 66560 (3 CTAs/SM)
    cudaFuncSetAttribute(mma_gemm<128,2,0,false,false,false>, cudaFuncAttributeMaxDynamicSharedMemorySize, SM_IN_2ST);
    cudaFuncSetAttribute(mma_gemm<128,3,2,false,false,false>, cudaFuncAttributeMaxDynamicSharedMemorySize, SM_A1B1_128);
    cudaFuncSetAttribute(mma_gemm<128,3,3,false,false,false>, cudaFuncAttributeMaxDynamicSharedMemorySize, SM_A1B1_128);
    cudaFuncSetAttribute(mma_gemm<64,3,0,true,true,true>,     cudaFuncAttributeMaxDynamicSharedMemorySize, SM_A2B2_64);
    cudaFuncSetAttribute(mma_gemm<128,3,1,true,true,false>,   cudaFuncAttributeMaxDynamicSharedMemorySize, SM_A2B2_128_S1);

    const int MT = MROWS / 128;  // 49

    // ---- weight packing ----
    transpose_h<<<dim3(12, 48, 24), 256>>>(in_w, inw_h, 384, 1536);
    transpose_h<<<dim3(48, 12, 12), 256>>>(out_w, outw_h, 1536, 384);
    half_copy<<<(DM*768 + 255)/256, 256>>>(patch_w, pw_h, DM*768);
    transpose_split<<<dim3(24, 2, 24), 256>>>(xproj_w, xpw_h, xpw_l, 768, 56, 64, 768);
    transpose_split<<<dim3(2, 24, 24), 256>>>(dt_w, dtw_h, dtw_l, 24, 768, 768, 64);

    // ---- patch embedding ----
    im2col_kernel<<<(MROWS * 768 + 255) / 256, 256>>>(images);
    mma_gemm<128,3,3,false,false,false><<<dim3(3, MT, 1), 256, SM_A1B1_128>>>(
        im_h, nullptr, 768, 0,  pw_h, nullptr, 768, 0,
        x, DM, 0, DM,  768/64,  patch_b, 0, pos_emb, nullptr, nullptr);

    for (int layer = 0; layer < DEPTH; layer++) {
        ln_kernel<<<MROWS, 128>>>(x, xn_h,
                                  ln_g + (size_t)layer * DM, ln_b + (size_t)layer * DM);

        // xz[dir] = xn @ in_w^T  (2-stage ring: 66.5 KB smem -> 3 CTAs/SM, 4->2.7 waves)
        mma_gemm<128,2,0,false,false,false><<<dim3(12, MT, 2), 256, SM_IN_2ST>>>(
            xn_h, nullptr, DM, 0,
            inw_h + (size_t)layer * 2 * 2*DI * DM, nullptr, DM, (long)2*DI * DM,
            xz, 2*DI, (long)MROWS * 2*DI, 2*DI,
            DM/64, nullptr, 0, nullptr, nullptr, nullptr);

        // conv: 4 channels/thread (R11-proven parallel form)
        conv_silu<<<(2 * MROWS * (DI/4) + 255) / 256, 256>>>(
            xz, conv_w + (size_t)layer * 2 * DI * 4, conv_b + (size_t)layer * 2 * DI,
            u_h, u_l);

        // dbc = u @ xproj_w  (split A and B: scan-critical)
        mma_gemm<64,3,0,true,true,true><<<dim3(1, MT, 2), 256, SM_A2B2_64>>>(
            u_h, u_l, DI, (long)MROWS * DI,
            xpw_h + (size_t)layer * 2 * 64 * DI,
            xpw_l + (size_t)layer * 2 * 64 * DI, DI, (long)64 * DI,
            dbcv, DBCN, (long)MROWS * DBCN, DBCN,
            DI/64, nullptr, 0, nullptr, dbch, dbcl);

        // dt = softplus(dbc[:, :24] @ dt_w + dt_b)  (S=1 -> single-stage smem, 3 CTAs/SM)
        mma_gemm<128,3,1,true,true,false><<<dim3(6, MT, 2), 256, SM_A2B2_128_S1>>>(
            dbch, dbcl, DBCN, (long)MROWS * DBCN,
            dtw_h + (size_t)layer * 2 * DI * 64,
            dtw_l + (size_t)layer * 2 * DI * 64, 64, (long)DI * 64,
            dtv, DI, (long)MROWS * DI, DI,
            1, dt_b + (size_t)layer * 2 * DI, (long)DI, nullptr, nullptr, nullptr);

        scan_kernel<<<dim3(6, BATCHN, 2), 128>>>(
            dtv, u_h, u_l, dbcv, xz,
            A_log + (size_t)layer * 2 * DI * DS, Dp + (size_t)layer * 2 * DI,
            y_h);

        // x += y @ out_w  (single-plane, dirs stacked K=1536; 147 CTAs = 1 wave, 3-stage)
        mma_gemm<128,3,2,false,false,false><<<dim3(3, MT, 1), 256, SM_A1B1_128>>>(
            y_h, nullptr, 2*DI, 0,
            outw_h + (size_t)layer * DM * 2*DI, nullptr, 2*DI, 0,
            x, DM, 0, DM,
            2*DI/64, nullptr, 0, x, nullptr, nullptr);
    }

    // final LN (fp32, into xz scratch) + pool + heads
    ln_f32<<<MROWS, 128>>>(x, xz, fln_g, fln_b);
    pool_head<<<BATCHN, 384>>>(xz, hdev_w, hdev_b, hdist_w, hdist_b, out);
    (void)in_sizes; (void)n_in; (void)out_size;
}